// round 4
// baseline (speedup 1.0000x reference)
#include <cuda_runtime.h>
#include <math.h>

// Problem constants
#define BB 8
#define SS 4096
#define DD 256
#define GG 3
#define NORD 2
#define NF 8192          // FFT length = 2*S
#define LOG2NF 13

// ---------------- device scratch (static, no allocation) ----------------
__device__ float  g_minpos[BB];
__device__ float2 g_tw[NF/2];                      // twiddles e^{-2pi i k / NF}
__device__ float  g_Wc[3 * 256 * 768];             // [tap][d][c] folded proj*conv weights
__device__ float  g_z[BB * GG * DD * SS];          // [b][g][d][s]  masked conv output
__device__ float  g_t[BB * SS * DD];               // rope output, later LN+gelu output
__device__ float  g_h1[BB * SS * DD];              // GEMM1 output
__device__ float  g_hh[BB * SS * 2 * DD];          // GEMM2 output
__device__ float  g_h[NORD * BB * DD * SS];        // [n][b][d][s] normalized filters
__device__ float  g_v[BB * DD * SS];               // [b][d][s] running v

// ---------------- init kernels ----------------
__global__ void tw_init_kernel() {
    int k = blockIdx.x * blockDim.x + threadIdx.x;
    if (k < NF/2) {
        double a = -2.0 * 3.14159265358979323846 * (double)k / (double)NF;
        double s, c;
        sincos(a, &s, &c);
        g_tw[k] = make_float2((float)c, (float)s);
    }
}

__global__ void minpos_kernel(const int* __restrict__ pos) {
    int b = blockIdx.x;
    int t = threadIdx.x;
    int local = 0x7fffffff;
    for (int s = t; s < SS; s += blockDim.x) {
        int p = pos[b * SS + s];
        if (p != -1) local = min(local, p);
    }
    for (int o = 16; o > 0; o >>= 1) local = min(local, __shfl_down_sync(0xffffffffu, local, o));
    __shared__ int wmin[8];
    if ((t & 31) == 0) wmin[t >> 5] = local;
    __syncthreads();
    if (t == 0) {
        int m = wmin[0];
        for (int i = 1; i < (int)(blockDim.x >> 5); i++) m = min(m, wmin[i]);
        g_minpos[b] = (float)m;
    }
}

// Wc[tap][d][c] = sum_i W_proj[d, g*256+i] * conv_w[c, i, tap],  g = c/256
__global__ void wc_kernel(const float* __restrict__ Wproj, const float* __restrict__ convw) {
    int idx = blockIdx.x * blockDim.x + threadIdx.x;
    if (idx >= 3 * 256 * 768) return;
    int k = idx / (256 * 768);
    int r = idx % (256 * 768);
    int d = r / 768;
    int c = r % 768;
    int g = c >> 8;
    const float* wp = Wproj + d * 768 + g * 256;
    const float* cw = convw + c * 768 + k;   // conv_w[c][i][k], stride 3 in i
    float acc = 0.f;
    #pragma unroll 8
    for (int i = 0; i < 256; i++) acc += wp[i] * cw[i * 3];
    g_Wc[idx] = acc;
}

// ---------------- rope ----------------
__global__ void rope_kernel(const float* __restrict__ emb, const int* __restrict__ pos) {
    int row = blockIdx.x;            // b*S + s
    int i = threadIdx.x;             // pair index 0..127
    int b = row >> 12;
    float2 xv = *(const float2*)(emb + (size_t)row * 256 + 2 * i);
    float frac = (float)i * (1.0f / 128.0f);
    float theta = 1.0f / powf(10000.0f, frac);
    int p = pos[row];
    float adj = (p == -1) ? -1.0f : ((float)p - g_minpos[b]);
    float ang = adj * theta;
    float sn, cs;
    sincosf(ang, &sn, &cs);
    float2 r;
    r.x = xv.x * cs - xv.y * sn;
    r.y = xv.x * sn + xv.y * cs;
    *(float2*)(g_t + (size_t)row * 256 + 2 * i) = r;
}

// ---------------- GEMM tiles: 64x64x16, 256 threads, 4x4 micro ----------------
#define GEMM_CORE()                                                        \
    __syncthreads();                                                       \
    _Pragma("unroll")                                                      \
    for (int kk = 0; kk < 16; kk++) {                                      \
        float4 af = *(const float4*)&As[kk][ty * 4];                       \
        float4 bf = *(const float4*)&Bs[kk][tx * 4];                       \
        float ar[4] = {af.x, af.y, af.z, af.w};                            \
        float br[4] = {bf.x, bf.y, bf.z, bf.w};                            \
        _Pragma("unroll")                                                  \
        for (int i = 0; i < 4; i++)                                        \
            _Pragma("unroll")                                              \
            for (int j = 0; j < 4; j++) acc[i][j] += ar[i] * br[j];        \
    }                                                                      \
    __syncthreads();

// zconv: z[b,c,s] = mask * ( conv_b[c] + sum_{kk<768} A[s][kk] * Wc[kk][c] )
// A[s][tap*256+d] = emb[b, s+tap-1, d]  (zero outside [0,S))
__global__ void zconv_gemm(const float* __restrict__ emb, const float* __restrict__ convb,
                           const int* __restrict__ pos) {
    __shared__ __align__(16) float As[16][64];
    __shared__ __align__(16) float Bs[16][64];
    int t = threadIdx.x;
    int tx = t & 15, ty = t >> 4;
    int n0 = blockIdx.x * 64;
    int by = blockIdx.y;
    int b = by >> 6;
    int s0 = (by & 63) * 64;
    int am = t >> 2, akq = t & 3;
    int bk = t >> 4, bnq = t & 15;
    float acc[4][4] = {};
    for (int k0 = 0; k0 < 768; k0 += 16) {
        int tap = k0 >> 8;
        int dq = (k0 & 255) + akq * 4;
        int sp = s0 + am + tap - 1;
        float4 av = make_float4(0.f, 0.f, 0.f, 0.f);
        if (sp >= 0 && sp < SS)
            av = *(const float4*)(emb + ((size_t)(b * SS + sp)) * 256 + dq);
        As[akq * 4 + 0][am] = av.x;
        As[akq * 4 + 1][am] = av.y;
        As[akq * 4 + 2][am] = av.z;
        As[akq * 4 + 3][am] = av.w;
        float4 bv = *(const float4*)(g_Wc + (size_t)(k0 + bk) * 768 + n0 + bnq * 4);
        *(float4*)&Bs[bk][bnq * 4] = bv;
        GEMM_CORE()
    }
    int srow = s0 + ty * 4;
    float m4[4];
    #pragma unroll
    for (int i = 0; i < 4; i++) m4[i] = (pos[b * SS + srow + i] != -1) ? 1.f : 0.f;
    #pragma unroll
    for (int j = 0; j < 4; j++) {
        int c = n0 + tx * 4 + j;
        float bias = convb[c];
        int ch = (b * 3 + (c >> 8)) * 256 + (c & 255);
        float4 v;
        v.x = (acc[0][j] + bias) * m4[0];
        v.y = (acc[1][j] + bias) * m4[1];
        v.z = (acc[2][j] + bias) * m4[2];
        v.w = (acc[3][j] + bias) * m4[3];
        *(float4*)(g_z + (size_t)ch * SS + srow) = v;
    }
}

// gemm1: g_h1 = g_t @ W1 + b1      (M=32768, N=256, K=256)
__global__ void gemm1_kernel(const float* __restrict__ W1, const float* __restrict__ b1) {
    __shared__ __align__(16) float As[16][64];
    __shared__ __align__(16) float Bs[16][64];
    int t = threadIdx.x;
    int tx = t & 15, ty = t >> 4;
    int n0 = blockIdx.x * 64;
    int r0 = blockIdx.y * 64;
    int am = t >> 2, akq = t & 3;
    int bk = t >> 4, bnq = t & 15;
    float acc[4][4] = {};
    for (int k0 = 0; k0 < 256; k0 += 16) {
        float4 av = *(const float4*)(g_t + (size_t)(r0 + am) * 256 + k0 + akq * 4);
        As[akq * 4 + 0][am] = av.x;
        As[akq * 4 + 1][am] = av.y;
        As[akq * 4 + 2][am] = av.z;
        As[akq * 4 + 3][am] = av.w;
        float4 bv = *(const float4*)(W1 + (size_t)(k0 + bk) * 256 + n0 + bnq * 4);
        *(float4*)&Bs[bk][bnq * 4] = bv;
        GEMM_CORE()
    }
    int cb = n0 + tx * 4;
    float4 bias = *(const float4*)(b1 + cb);
    #pragma unroll
    for (int i = 0; i < 4; i++) {
        int row = r0 + ty * 4 + i;
        float4 v;
        v.x = acc[i][0] + bias.x;
        v.y = acc[i][1] + bias.y;
        v.z = acc[i][2] + bias.z;
        v.w = acc[i][3] + bias.w;
        *(float4*)(g_h1 + (size_t)row * 256 + cb) = v;
    }
}

// LayerNorm (two-pass) + exact gelu: reads g_h1, writes g_t
__global__ void ln_gelu_kernel(const float* __restrict__ lng, const float* __restrict__ lnb) {
    int row = blockIdx.x;
    int t = threadIdx.x;
    float v = g_h1[(size_t)row * 256 + t];
    __shared__ float ws[8];
    float s1 = v;
    for (int o = 16; o > 0; o >>= 1) s1 += __shfl_down_sync(0xffffffffu, s1, o);
    if ((t & 31) == 0) ws[t >> 5] = s1;
    __syncthreads();
    if (t == 0) {
        float a = 0.f;
        for (int i = 0; i < 8; i++) a += ws[i];
        ws[0] = a;
    }
    __syncthreads();
    float mu = ws[0] * (1.f / 256.f);
    __syncthreads();
    float dv = v - mu;
    float s2 = dv * dv;
    for (int o = 16; o > 0; o >>= 1) s2 += __shfl_down_sync(0xffffffffu, s2, o);
    if ((t & 31) == 0) ws[t >> 5] = s2;
    __syncthreads();
    if (t == 0) {
        float a = 0.f;
        for (int i = 0; i < 8; i++) a += ws[i];
        ws[0] = a;
    }
    __syncthreads();
    float var = ws[0] * (1.f / 256.f);
    float xn = dv / sqrtf(var + 1e-5f) * lng[t] + lnb[t];
    float ge = 0.5f * xn * (1.f + erff(xn / sqrtf(2.0f)));
    g_t[(size_t)row * 256 + t] = ge;
}

// gemm2: g_hh = (g_t @ W2 + b2) * ff_scale   (M=32768, N=512, K=256)
__global__ void gemm2_kernel(const float* __restrict__ W2, const float* __restrict__ b2,
                             const float* __restrict__ ffs) {
    __shared__ __align__(16) float As[16][64];
    __shared__ __align__(16) float Bs[16][64];
    int t = threadIdx.x;
    int tx = t & 15, ty = t >> 4;
    int n0 = blockIdx.x * 64;
    int r0 = blockIdx.y * 64;
    int am = t >> 2, akq = t & 3;
    int bk = t >> 4, bnq = t & 15;
    float acc[4][4] = {};
    for (int k0 = 0; k0 < 256; k0 += 16) {
        float4 av = *(const float4*)(g_t + (size_t)(r0 + am) * 256 + k0 + akq * 4);
        As[akq * 4 + 0][am] = av.x;
        As[akq * 4 + 1][am] = av.y;
        As[akq * 4 + 2][am] = av.z;
        As[akq * 4 + 3][am] = av.w;
        float4 bv = *(const float4*)(W2 + (size_t)(k0 + bk) * 512 + n0 + bnq * 4);
        *(float4*)&Bs[bk][bnq * 4] = bv;
        GEMM_CORE()
    }
    int cb = n0 + tx * 4;
    float4 bias = *(const float4*)(b2 + cb);
    float4 sc   = *(const float4*)(ffs + cb);
    #pragma unroll
    for (int i = 0; i < 4; i++) {
        int row = r0 + ty * 4 + i;
        float4 v;
        v.x = (acc[i][0] + bias.x) * sc.x;
        v.y = (acc[i][1] + bias.y) * sc.y;
        v.z = (acc[i][2] + bias.z) * sc.z;
        v.w = (acc[i][3] + bias.w) * sc.w;
        *(float4*)(g_hh + (size_t)row * 512 + cb) = v;
    }
}

// normalize filters: g_h[n][b][d][s] = hh[row][n*256+d] / (sum_d|.| + 1e-8)
__global__ void hhat_kernel() {
    int row = blockIdx.x;
    int t = threadIdx.x;
    int b = row >> 12;
    int s = row & 4095;
    __shared__ float ws[8];
    for (int n = 0; n < NORD; n++) {
        float v = g_hh[(size_t)row * 512 + n * 256 + t];
        float a = fabsf(v);
        for (int o = 16; o > 0; o >>= 1) a += __shfl_down_sync(0xffffffffu, a, o);
        if ((t & 31) == 0) ws[t >> 5] = a;
        __syncthreads();
        if (t == 0) {
            float su = 0.f;
            for (int i = 0; i < 8; i++) su += ws[i];
            ws[0] = su;
        }
        __syncthreads();
        float den = ws[0] + 1e-8f;
        g_h[(size_t)n * (BB * DD * SS) + (size_t)(b * 256 + t) * SS + s] = v / den;
        __syncthreads();
    }
}

// ---------------- FFT causal conv, channel-pair packing ----------------
// One block per channel PAIR (d0, d0+1). Two forward packed FFTs:
//   sa = FFT(x_{d0} + i x_{d0+1}),  sb = FFT(f_{d0} + i f_{d0+1})
// Hermitian split each (like-magnitude packing -> no catastrophic cross-talk),
// per-channel spectral product, repack G = Y_{d0} + i Y_{d0+1}, one inverse FFT.
// Real part -> conv result for d0, imag -> d0+1.
__global__ void fftconv2_kernel(int iter) {
    extern __shared__ float2 smbuf[];
    float2* sa = smbuf;            // NF complex (x pair)
    float2* sb = smbuf + NF;       // NF complex (f pair)
    float2* tw = smbuf + 2 * NF;   // NF/2 twiddles
    int t = threadIdx.x;
    int pi = blockIdx.x;           // 0..1023
    int b = pi >> 7;
    int d0 = (pi & 127) * 2;
    const float* xp = (iter == 0) ? (g_z + (size_t)((b * 3 + 2) * 256 + d0) * SS)
                                  : (g_v + (size_t)(b * 256 + d0) * SS);
    const float* fp = g_h + (size_t)iter * (BB * DD * SS) + (size_t)(b * 256 + d0) * SS;
    const float* zp = g_z + (size_t)((b * 3 + iter) * 256 + d0) * SS;
    float* op = g_v + (size_t)(b * 256 + d0) * SS;

    for (int i = t; i < NF / 2; i += blockDim.x) tw[i] = g_tw[i];
    for (int s = t; s < SS; s += blockDim.x) {
        sa[s] = make_float2(xp[s], xp[SS + s]);
        sb[s] = make_float2(fp[s], fp[SS + s]);
    }
    for (int s = SS + t; s < NF; s += blockDim.x) {
        sa[s] = make_float2(0.f, 0.f);
        sb[s] = make_float2(0.f, 0.f);
    }
    __syncthreads();

    // forward DIF on both arrays (natural in -> bit-reversed out)
    for (int m = NF; m >= 2; m >>= 1) {
        int half = m >> 1;
        int tstep = NF / m;
        for (int i = t; i < NF / 2; i += blockDim.x) {
            int j = i & (half - 1);
            int p = 2 * i - j;
            int q = p + half;
            float2 w = tw[j * tstep];
            float2 a = sa[p], bb = sa[q];
            float sx = a.x - bb.x, sy = a.y - bb.y;
            sa[p] = make_float2(a.x + bb.x, a.y + bb.y);
            sa[q] = make_float2(sx * w.x - sy * w.y, sx * w.y + sy * w.x);
            float2 c = sb[p], dd = sb[q];
            float ux = c.x - dd.x, uy = c.y - dd.y;
            sb[p] = make_float2(c.x + dd.x, c.y + dd.y);
            sb[q] = make_float2(ux * w.x - uy * w.y, ux * w.y + uy * w.x);
        }
        __syncthreads();
    }

    // per-channel spectral product in bit-reversed domain, result packed into sa
    for (int k = t; k < NF / 2; k += blockDim.x) {
        if (k == 0) {
            float2 A0 = sa[0], B0 = sb[0];
            sa[0] = make_float2(A0.x * B0.x, A0.y * B0.y);    // bin 0 (all real)
            float2 A1 = sa[1], B1 = sb[1];
            sa[1] = make_float2(A1.x * B1.x, A1.y * B1.y);    // bin NF/2 (all real)
        } else {
            int p = __brev((unsigned)k) >> (32 - LOG2NF);
            int q = __brev((unsigned)(NF - k)) >> (32 - LOG2NF);
            float2 A = sa[p], Ac = sa[q];
            float2 Bv = sb[p], Bc = sb[q];
            float Xr  = 0.5f * (A.x + Ac.x),  Xi  = 0.5f * (A.y - Ac.y);
            float Xpr = 0.5f * (A.y + Ac.y),  Xpi = 0.5f * (Ac.x - A.x);
            float Fr  = 0.5f * (Bv.x + Bc.x), Fi  = 0.5f * (Bv.y - Bc.y);
            float Fpr = 0.5f * (Bv.y + Bc.y), Fpi = 0.5f * (Bc.x - Bv.x);
            float Yr  = Xr * Fr - Xi * Fi,    Yi  = Xr * Fi + Xi * Fr;
            float Ypr = Xpr * Fpr - Xpi * Fpi, Ypi = Xpr * Fpi + Xpi * Fpr;
            sa[p] = make_float2(Yr - Ypi, Yi + Ypr);          // G[k]    = Y + iY'
            sa[q] = make_float2(Yr + Ypi, Ypr - Yi);          // G[NF-k] = conj(Y) + i conj(Y')
        }
    }
    __syncthreads();

    // inverse DIT (conj twiddles), bit-reversed in -> natural out, unnormalized
    for (int m = 2; m <= NF; m <<= 1) {
        int half = m >> 1;
        int tstep = NF / m;
        for (int i = t; i < NF / 2; i += blockDim.x) {
            int j = i & (half - 1);
            int p = 2 * i - j;
            int q = p + half;
            float2 a = sa[p], bb = sa[q];
            float2 w = tw[j * tstep];
            float tx_ = bb.x * w.x + bb.y * w.y;   // bb * conj(w)
            float ty_ = bb.y * w.x - bb.x * w.y;
            sa[p] = make_float2(a.x + tx_, a.y + ty_);
            sa[q] = make_float2(a.x - tx_, a.y - ty_);
        }
        __syncthreads();
    }

    // unnormalized fwd+inv gives NF*circconv; reference scales by 1/NF -> total 1/NF^2
    const float scale = 1.0f / (8192.0f * 8192.0f);
    for (int s = t; s < SS; s += blockDim.x) {
        float2 r = sa[s];
        op[s]      = zp[s]      * (r.x * scale);
        op[SS + s] = zp[SS + s] * (r.y * scale);
    }
}

// out[b,s,e] = mask * (sum_d v[b][d][s] * W_out[d][e] + b_out[e])
__global__ void out_gemm(const float* __restrict__ Wout, const float* __restrict__ bout,
                         const int* __restrict__ pos, float* __restrict__ out) {
    __shared__ __align__(16) float As[16][64];
    __shared__ __align__(16) float Bs[16][64];
    int t = threadIdx.x;
    int tx = t & 15, ty = t >> 4;
    int n0 = blockIdx.x * 64;
    int by = blockIdx.y;
    int b = by >> 6;
    int s0 = (by & 63) * 64;
    int dk = t >> 4, sq = t & 15;
    int bk = t >> 4, bnq = t & 15;
    float acc[4][4] = {};
    const float* vb = g_v + (size_t)b * 256 * SS;
    for (int k0 = 0; k0 < 256; k0 += 16) {
        float4 av = *(const float4*)(vb + (size_t)(k0 + dk) * SS + s0 + sq * 4);
        *(float4*)&As[dk][sq * 4] = av;
        float4 bv = *(const float4*)(Wout + (size_t)(k0 + bk) * 256 + n0 + bnq * 4);
        *(float4*)&Bs[bk][bnq * 4] = bv;
        GEMM_CORE()
    }
    int cb = n0 + tx * 4;
    float4 bias = *(const float4*)(bout + cb);
    #pragma unroll
    for (int i = 0; i < 4; i++) {
        int s = s0 + ty * 4 + i;
        float m = (pos[b * SS + s] != -1) ? 1.f : 0.f;
        float4 v;
        v.x = (acc[i][0] + bias.x) * m;
        v.y = (acc[i][1] + bias.y) * m;
        v.z = (acc[i][2] + bias.z) * m;
        v.w = (acc[i][3] + bias.w) * m;
        *(float4*)(out + ((size_t)(b * SS + s)) * 256 + cb) = v;
    }
}

// ---------------- launch ----------------
extern "C" void kernel_launch(void* const* d_in, const int* in_sizes, int n_in,
                              void* d_out, int out_size) {
    const float* emb   = (const float*)d_in[0];
    const int*   pos   = (const int*)d_in[1];
    const float* Wproj = (const float*)d_in[2];
    const float* convw = (const float*)d_in[3];
    const float* convb = (const float*)d_in[4];
    const float* W1    = (const float*)d_in[5];
    const float* b1    = (const float*)d_in[6];
    const float* lng   = (const float*)d_in[7];
    const float* lnb   = (const float*)d_in[8];
    const float* W2    = (const float*)d_in[9];
    const float* b2    = (const float*)d_in[10];
    const float* ffs   = (const float*)d_in[11];
    const float* Wout  = (const float*)d_in[12];
    const float* bout  = (const float*)d_in[13];
    float* out = (float*)d_out;

    cudaFuncSetAttribute(fftconv2_kernel, cudaFuncAttributeMaxDynamicSharedMemorySize, 163840);

    tw_init_kernel<<<16, 256>>>();
    minpos_kernel<<<BB, 256>>>(pos);
    wc_kernel<<<(3 * 256 * 768 + 255) / 256, 256>>>(Wproj, convw);
    rope_kernel<<<BB * SS, 128>>>(emb, pos);
    zconv_gemm<<<dim3(768 / 64, BB * (SS / 64)), 256>>>(emb, convb, pos);
    gemm1_kernel<<<dim3(256 / 64, (BB * SS) / 64), 256>>>(W1, b1);
    ln_gelu_kernel<<<BB * SS, 256>>>(lng, lnb);
    gemm2_kernel<<<dim3(512 / 64, (BB * SS) / 64), 256>>>(W2, b2, ffs);
    hhat_kernel<<<BB * SS, 256>>>();
    fftconv2_kernel<<<BB * DD / 2, 512, 163840>>>(0);
    fftconv2_kernel<<<BB * DD / 2, 512, 163840>>>(1);
    out_gemm<<<dim3(256 / 64, BB * (SS / 64)), 256>>>(Wout, bout, pos, out);
}

// round 6
// speedup vs baseline: 2.7591x; 2.7591x over previous
#include <cuda_runtime.h>
#include <math.h>
#include <stdint.h>

// Problem constants
#define BB 8
#define SS 4096
#define DD 256
#define GG 3
#define NORD 2
#define NF 8192          // FFT length = 2*S
#define LOG2NF 13

// ---------------- device scratch (static, no allocation) ----------------
__device__ float  g_minpos[BB];
__device__ float2 g_tw[NF/2];                      // twiddles e^{-2pi i k / NF}
__device__ float  g_cwT[3 * 256 * 768];            // [tap][i][c] transposed conv weights
__device__ float  g_Wc[3 * 256 * 768];             // [tap*256+d][c] folded proj*conv weights
__device__ float  g_z[BB * GG * DD * SS];          // [b][g][d][s]  masked conv output
__device__ float  g_t[BB * SS * DD];               // rope output, later LN+gelu output
__device__ float  g_h1[BB * SS * DD];              // GEMM1 output
__device__ float  g_hh[BB * SS * 2 * DD];          // GEMM2 output
__device__ float  g_h[NORD * BB * DD * SS];        // [n][b][d][s] normalized filters
__device__ float  g_v[BB * DD * SS];               // [b][d][s] running v
__device__ float  g_vT[BB * SS * DD];              // [b][s][d] transposed v for out gemm

// ---------------- helpers ----------------
__device__ __forceinline__ uint32_t sptr(const void* p) {
    return (uint32_t)__cvta_generic_to_shared(p);
}
__device__ __forceinline__ void cpa16(uint32_t dst, const void* src, int sz) {
    asm volatile("cp.async.ca.shared.global [%0], [%1], 16, %2;\n"
                 :: "r"(dst), "l"(src), "r"(sz));
}
__device__ __forceinline__ void cpa_commit() {
    asm volatile("cp.async.commit_group;\n" ::: "memory");
}
__device__ __forceinline__ void cpa_wait1() {
    asm volatile("cp.async.wait_group 1;\n" ::: "memory");
}
__device__ __forceinline__ void cpa_wait0() {
    asm volatile("cp.async.wait_group 0;\n" ::: "memory");
}
__device__ __forceinline__ void tf32_split(float v, uint32_t &h, uint32_t &l) {
    float hf;
    asm("cvt.rna.tf32.f32 %0, %1;" : "=f"(hf) : "f"(v));
    h = __float_as_uint(hf);
    l = __float_as_uint(v - hf);
}
__device__ __forceinline__ void mma8(float c[4], const uint32_t a[4], const uint32_t b[2]) {
    asm volatile(
        "mma.sync.aligned.m16n8k8.row.col.f32.tf32.tf32.f32 "
        "{%0,%1,%2,%3}, {%4,%5,%6,%7}, {%8,%9}, {%0,%1,%2,%3};\n"
        : "+f"(c[0]), "+f"(c[1]), "+f"(c[2]), "+f"(c[3])
        : "r"(a[0]), "r"(a[1]), "r"(a[2]), "r"(a[3]), "r"(b[0]), "r"(b[1]));
}

// Compute one BK=16 slab: warp tile 32x32, 3-pass tf32 (err ~1e-6)
__device__ __forceinline__ void compute_slab16(
    const float (*As)[20], const float (*Bs)[72],
    int wm, int wn, int g, int tig, float acc[2][4][4])
{
    #pragma unroll
    for (int kb = 0; kb < 16; kb += 8) {
        uint32_t ah[2][4], al[2][4];
        #pragma unroll
        for (int mt = 0; mt < 2; mt++) {
            int rm = wm * 32 + mt * 16;
            tf32_split(As[rm + g][kb + tig],         ah[mt][0], al[mt][0]);
            tf32_split(As[rm + g + 8][kb + tig],     ah[mt][1], al[mt][1]);
            tf32_split(As[rm + g][kb + tig + 4],     ah[mt][2], al[mt][2]);
            tf32_split(As[rm + g + 8][kb + tig + 4], ah[mt][3], al[mt][3]);
        }
        uint32_t bh[4][2], bl[4][2];
        #pragma unroll
        for (int nt = 0; nt < 4; nt++) {
            int cn = wn * 32 + nt * 8 + g;
            tf32_split(Bs[kb + tig][cn],     bh[nt][0], bl[nt][0]);
            tf32_split(Bs[kb + tig + 4][cn], bh[nt][1], bl[nt][1]);
        }
        #pragma unroll
        for (int mt = 0; mt < 2; mt++)
            #pragma unroll
            for (int nt = 0; nt < 4; nt++) {
                mma8(acc[mt][nt], ah[mt], bh[nt]);
                mma8(acc[mt][nt], ah[mt], bl[nt]);
                mma8(acc[mt][nt], al[mt], bh[nt]);
            }
    }
}

// ---------------- init kernels ----------------
__global__ void tw_init_kernel() {
    int k = blockIdx.x * blockDim.x + threadIdx.x;
    if (k < NF/2) {
        double a = -2.0 * 3.14159265358979323846 * (double)k / (double)NF;
        double s, c;
        sincos(a, &s, &c);
        g_tw[k] = make_float2((float)c, (float)s);
    }
}

__global__ void minpos_kernel(const int* __restrict__ pos) {
    int b = blockIdx.x;
    int t = threadIdx.x;
    int local = 0x7fffffff;
    for (int s = t; s < SS; s += blockDim.x) {
        int p = pos[b * SS + s];
        if (p != -1) local = min(local, p);
    }
    for (int o = 16; o > 0; o >>= 1) local = min(local, __shfl_down_sync(0xffffffffu, local, o));
    __shared__ int wmin[8];
    if ((t & 31) == 0) wmin[t >> 5] = local;
    __syncthreads();
    if (t == 0) {
        int m = wmin[0];
        for (int i = 1; i < (int)(blockDim.x >> 5); i++) m = min(m, wmin[i]);
        g_minpos[b] = (float)m;
    }
}

// transpose conv_w -> cwT[tap][i][c]
__global__ void cwt_kernel(const float* __restrict__ convw) {
    int idx = blockIdx.x * blockDim.x + threadIdx.x;
    if (idx >= 3 * 256 * 768) return;
    int k = idx / (256 * 768);
    int r = idx % (256 * 768);
    int i = r / 768;
    int c = r % 768;
    g_cwT[idx] = convw[(size_t)c * 768 + i * 3 + k];
}

// ---------------- small SIMT gemm for Wc precompute ----------------
#define GEMM_CORE()                                                        \
    __syncthreads();                                                       \
    _Pragma("unroll")                                                      \
    for (int kk = 0; kk < 16; kk++) {                                      \
        float4 af = *(const float4*)&As[kk][ty * 4];                       \
        float4 bf = *(const float4*)&Bs[kk][tx * 4];                       \
        float ar[4] = {af.x, af.y, af.z, af.w};                            \
        float br[4] = {bf.x, bf.y, bf.z, bf.w};                            \
        _Pragma("unroll")                                                  \
        for (int i = 0; i < 4; i++)                                        \
            _Pragma("unroll")                                              \
            for (int j = 0; j < 4; j++) acc[i][j] += ar[i] * br[j];        \
    }                                                                      \
    __syncthreads();

// Wc[(tap*256 + d)][c] = sum_i Wproj[d][g*256+i] * cwT[tap][i][c],  g = c/256
__global__ void wc_gemm(const float* __restrict__ Wproj) {
    __shared__ __align__(16) float As[16][64];
    __shared__ __align__(16) float Bs[16][64];
    int t = threadIdx.x;
    int tx = t & 15, ty = t >> 4;
    int n0 = blockIdx.x * 64;         // c
    int m0 = blockIdx.y * 64;         // d
    int tap = blockIdx.z;
    int g = n0 >> 8;
    int am = t >> 2, akq = t & 3;
    int bk = t >> 4, bnq = t & 15;
    float acc[4][4] = {};
    for (int k0 = 0; k0 < 256; k0 += 16) {
        float4 av = *(const float4*)(Wproj + (size_t)(m0 + am) * 768 + g * 256 + k0 + akq * 4);
        As[akq * 4 + 0][am] = av.x;
        As[akq * 4 + 1][am] = av.y;
        As[akq * 4 + 2][am] = av.z;
        As[akq * 4 + 3][am] = av.w;
        float4 bv = *(const float4*)(g_cwT + (size_t)tap * 196608 + (size_t)(k0 + bk) * 768 + n0 + bnq * 4);
        *(float4*)&Bs[bk][bnq * 4] = bv;
        GEMM_CORE()
    }
    #pragma unroll
    for (int i = 0; i < 4; i++) {
        int d = m0 + ty * 4 + i;
        float4 v = make_float4(acc[i][0], acc[i][1], acc[i][2], acc[i][3]);
        *(float4*)(g_Wc + (size_t)(tap * 256 + d) * 768 + n0 + tx * 4) = v;
    }
}

// ---------------- rope ----------------
__global__ void rope_kernel(const float* __restrict__ emb, const int* __restrict__ pos) {
    int row = blockIdx.x;            // b*S + s
    int i = threadIdx.x;             // pair index 0..127
    int b = row >> 12;
    float2 xv = *(const float2*)(emb + (size_t)row * 256 + 2 * i);
    float frac = (float)i * (1.0f / 128.0f);
    float theta = 1.0f / powf(10000.0f, frac);
    int p = pos[row];
    float adj = (p == -1) ? -1.0f : ((float)p - g_minpos[b]);
    float ang = adj * theta;
    float sn, cs;
    sincosf(ang, &sn, &cs);
    float2 r;
    r.x = xv.x * cs - xv.y * sn;
    r.y = xv.x * sn + xv.y * cs;
    *(float2*)(g_t + (size_t)row * 256 + 2 * i) = r;
}

// ---------------- MMA GEMM: zconv (folded proj∘conv, im2col A) ----------------
// C[s, c] = mask[s] * (conv_b[c] + sum_{kk<768} A[s][kk] * Wc[kk][c])
// A[s][tap*256+d] = emb[b, s+tap-1, d]
__global__ __launch_bounds__(256, 2) void zconv_mma(
    const float* __restrict__ emb, const float* __restrict__ convb,
    const int* __restrict__ pos)
{
    __shared__ float As[2][128][20];
    __shared__ float Bs[2][16][72];
    int t = threadIdx.x;
    int w = t >> 5, lane = t & 31, g = lane >> 2, tig = lane & 3;
    int wm = w & 3, wn = w >> 2;
    int n0 = blockIdx.x * 64;
    int by = blockIdx.y;
    int b = by >> 5;
    int s0 = (by & 31) * 128;
    float acc[2][4][4] = {};

    auto issue = [&](int slab, int stage) {
        int k0 = slab * 16;
        int tap = k0 >> 8;
        #pragma unroll
        for (int p = 0; p < 2; p++) {
            int idx = t + p * 256;
            int r = idx >> 2, q = idx & 3;
            int sp = s0 + r + tap - 1;
            int ok = (sp >= 0 && sp < SS);
            int spc = min(max(sp, 0), SS - 1);
            const float* src = emb + (size_t)(b * SS + spc) * 256 + (k0 & 255) + q * 4;
            cpa16(sptr(&As[stage][r][q * 4]), src, ok ? 16 : 0);
        }
        {
            int k = t >> 4, nq = t & 15;
            const float* src = g_Wc + (size_t)(k0 + k) * 768 + n0 + nq * 4;
            cpa16(sptr(&Bs[stage][k][nq * 4]), src, 16);
        }
        cpa_commit();
    };

    issue(0, 0);
    const int KS = 48;
    for (int j = 0; j < KS; j++) {
        int st = j & 1;
        if (j + 1 < KS) { issue(j + 1, st ^ 1); cpa_wait1(); }
        else cpa_wait0();
        __syncthreads();
        compute_slab16(As[st], Bs[st], wm, wn, g, tig, acc);
        __syncthreads();
    }

    // epilogue: scattered per-channel writes to g_z[ch][s]
    #pragma unroll
    for (int mt = 0; mt < 2; mt++) {
        int sa = s0 + wm * 32 + mt * 16 + g;
        int sb = sa + 8;
        float ma = (pos[b * SS + sa] != -1) ? 1.f : 0.f;
        float mb = (pos[b * SS + sb] != -1) ? 1.f : 0.f;
        #pragma unroll
        for (int nt = 0; nt < 4; nt++) {
            int c0 = n0 + wn * 32 + nt * 8 + 2 * tig;
            int c1 = c0 + 1;
            float bias0 = __ldg(convb + c0);
            float bias1 = __ldg(convb + c1);
            size_t ch0 = (size_t)((b * 3 + (c0 >> 8)) * 256 + (c0 & 255)) * SS;
            size_t ch1 = (size_t)((b * 3 + (c1 >> 8)) * 256 + (c1 & 255)) * SS;
            g_z[ch0 + sa] = (acc[mt][nt][0] + bias0) * ma;
            g_z[ch1 + sa] = (acc[mt][nt][1] + bias1) * ma;
            g_z[ch0 + sb] = (acc[mt][nt][2] + bias0) * mb;
            g_z[ch1 + sb] = (acc[mt][nt][3] + bias1) * mb;
        }
    }
}

// ---------------- MMA GEMM: generic row-major (ffn1, ffn2, out) ----------------
// sel=0: A=g_t,  C=g_h1  (LDN=256)
// sel=1: A=g_t,  C=g_hh  (LDN=512, scale)
// sel=2: A=g_vT, C=Cout  (LDN=256, mask)
// NOTE: device globals are resolved INSIDE device code (host cannot pass their
// addresses as kernel args).
template<int LDN, bool SCALE, bool MASK>
__global__ __launch_bounds__(256, 2) void ffn_mma(
    int sel, const float* __restrict__ B,
    const float* __restrict__ bias, const float* __restrict__ scale,
    const int* __restrict__ pos, float* __restrict__ Cout)
{
    const float* A = (sel == 2) ? g_vT : g_t;
    float* C = (sel == 0) ? g_h1 : (sel == 1) ? g_hh : Cout;

    __shared__ float As[2][128][20];
    __shared__ float Bs[2][16][72];
    int t = threadIdx.x;
    int w = t >> 5, lane = t & 31, g = lane >> 2, tig = lane & 3;
    int wm = w & 3, wn = w >> 2;
    int n0 = blockIdx.x * 64;
    int r0 = blockIdx.y * 128;
    float acc[2][4][4] = {};

    auto issue = [&](int slab, int stage) {
        int k0 = slab * 16;
        #pragma unroll
        for (int p = 0; p < 2; p++) {
            int idx = t + p * 256;
            int r = idx >> 2, q = idx & 3;
            cpa16(sptr(&As[stage][r][q * 4]), A + (size_t)(r0 + r) * 256 + k0 + q * 4, 16);
        }
        {
            int k = t >> 4, nq = t & 15;
            cpa16(sptr(&Bs[stage][k][nq * 4]), B + (size_t)(k0 + k) * LDN + n0 + nq * 4, 16);
        }
        cpa_commit();
    };

    issue(0, 0);
    const int KS = 16;
    for (int j = 0; j < KS; j++) {
        int st = j & 1;
        if (j + 1 < KS) { issue(j + 1, st ^ 1); cpa_wait1(); }
        else cpa_wait0();
        __syncthreads();
        compute_slab16(As[st], Bs[st], wm, wn, g, tig, acc);
        __syncthreads();
    }

    #pragma unroll
    for (int mt = 0; mt < 2; mt++) {
        int ra = r0 + wm * 32 + mt * 16 + g;
        int rb = ra + 8;
        float ma = 1.f, mb = 1.f;
        if (MASK) {
            ma = (pos[ra] != -1) ? 1.f : 0.f;
            mb = (pos[rb] != -1) ? 1.f : 0.f;
        }
        #pragma unroll
        for (int nt = 0; nt < 4; nt++) {
            int cn = n0 + wn * 32 + nt * 8 + 2 * tig;
            float2 bi = *(const float2*)(bias + cn);
            float sx = 1.f, sy = 1.f;
            if (SCALE) {
                float2 sc = *(const float2*)(scale + cn);
                sx = sc.x; sy = sc.y;
            }
            float2 va, vb;
            va.x = (acc[mt][nt][0] + bi.x) * sx * ma;
            va.y = (acc[mt][nt][1] + bi.y) * sy * ma;
            vb.x = (acc[mt][nt][2] + bi.x) * sx * mb;
            vb.y = (acc[mt][nt][3] + bi.y) * sy * mb;
            *(float2*)(C + (size_t)ra * LDN + cn) = va;
            *(float2*)(C + (size_t)rb * LDN + cn) = vb;
        }
    }
}

// LayerNorm (two-pass) + exact gelu: reads g_h1, writes g_t
__global__ void ln_gelu_kernel(const float* __restrict__ lng, const float* __restrict__ lnb) {
    int row = blockIdx.x;
    int t = threadIdx.x;
    float v = g_h1[(size_t)row * 256 + t];
    __shared__ float ws[8];
    float s1 = v;
    for (int o = 16; o > 0; o >>= 1) s1 += __shfl_down_sync(0xffffffffu, s1, o);
    if ((t & 31) == 0) ws[t >> 5] = s1;
    __syncthreads();
    if (t == 0) {
        float a = 0.f;
        for (int i = 0; i < 8; i++) a += ws[i];
        ws[0] = a;
    }
    __syncthreads();
    float mu = ws[0] * (1.f / 256.f);
    __syncthreads();
    float dv = v - mu;
    float s2 = dv * dv;
    for (int o = 16; o > 0; o >>= 1) s2 += __shfl_down_sync(0xffffffffu, s2, o);
    if ((t & 31) == 0) ws[t >> 5] = s2;
    __syncthreads();
    if (t == 0) {
        float a = 0.f;
        for (int i = 0; i < 8; i++) a += ws[i];
        ws[0] = a;
    }
    __syncthreads();
    float var = ws[0] * (1.f / 256.f);
    float xn = dv / sqrtf(var + 1e-5f) * lng[t] + lnb[t];
    float ge = 0.5f * xn * (1.f + erff(xn / sqrtf(2.0f)));
    g_t[(size_t)row * 256 + t] = ge;
}

// normalize filters: g_h[n][b][d][s] = hh[row][n*256+d] / (sum_d|.| + 1e-8)
__global__ void hhat_kernel() {
    int row = blockIdx.x;
    int t = threadIdx.x;
    int b = row >> 12;
    int s = row & 4095;
    __shared__ float ws[8];
    for (int n = 0; n < NORD; n++) {
        float v = g_hh[(size_t)row * 512 + n * 256 + t];
        float a = fabsf(v);
        for (int o = 16; o > 0; o >>= 1) a += __shfl_down_sync(0xffffffffu, a, o);
        if ((t & 31) == 0) ws[t >> 5] = a;
        __syncthreads();
        if (t == 0) {
            float su = 0.f;
            for (int i = 0; i < 8; i++) su += ws[i];
            ws[0] = su;
        }
        __syncthreads();
        float den = ws[0] + 1e-8f;
        g_h[(size_t)n * (BB * DD * SS) + (size_t)(b * 256 + t) * SS + s] = v / den;
        __syncthreads();
    }
}

// ---------------- FFT causal conv, channel-pair packing ----------------
__global__ void fftconv2_kernel(int iter) {
    extern __shared__ float2 smbuf[];
    float2* sa = smbuf;            // NF complex (x pair)
    float2* sb = smbuf + NF;       // NF complex (f pair)
    float2* tw = smbuf + 2 * NF;   // NF/2 twiddles
    int t = threadIdx.x;
    int pi = blockIdx.x;           // 0..1023
    int b = pi >> 7;
    int d0 = (pi & 127) * 2;
    const float* xp = (iter == 0) ? (g_z + (size_t)((b * 3 + 2) * 256 + d0) * SS)
                                  : (g_v + (size_t)(b * 256 + d0) * SS);
    const float* fp = g_h + (size_t)iter * (BB * DD * SS) + (size_t)(b * 256 + d0) * SS;
    const float* zp = g_z + (size_t)((b * 3 + iter) * 256 + d0) * SS;
    float* op = g_v + (size_t)(b * 256 + d0) * SS;

    for (int i = t; i < NF / 2; i += blockDim.x) tw[i] = g_tw[i];
    for (int s = t; s < SS; s += blockDim.x) {
        sa[s] = make_float2(xp[s], xp[SS + s]);
        sb[s] = make_float2(fp[s], fp[SS + s]);
    }
    for (int s = SS + t; s < NF; s += blockDim.x) {
        sa[s] = make_float2(0.f, 0.f);
        sb[s] = make_float2(0.f, 0.f);
    }
    __syncthreads();

    // forward DIF on both arrays (natural in -> bit-reversed out)
    for (int m = NF; m >= 2; m >>= 1) {
        int half = m >> 1;
        int tstep = NF / m;
        for (int i = t; i < NF / 2; i += blockDim.x) {
            int j = i & (half - 1);
            int p = 2 * i - j;
            int q = p + half;
            float2 w = tw[j * tstep];
            float2 a = sa[p], bb = sa[q];
            float sx = a.x - bb.x, sy = a.y - bb.y;
            sa[p] = make_float2(a.x + bb.x, a.y + bb.y);
            sa[q] = make_float2(sx * w.x - sy * w.y, sx * w.y + sy * w.x);
            float2 c = sb[p], dd = sb[q];
            float ux = c.x - dd.x, uy = c.y - dd.y;
            sb[p] = make_float2(c.x + dd.x, c.y + dd.y);
            sb[q] = make_float2(ux * w.x - uy * w.y, ux * w.y + uy * w.x);
        }
        __syncthreads();
    }

    // per-channel spectral product in bit-reversed domain, result packed into sa
    for (int k = t; k < NF / 2; k += blockDim.x) {
        if (k == 0) {
            float2 A0 = sa[0], B0 = sb[0];
            sa[0] = make_float2(A0.x * B0.x, A0.y * B0.y);    // bin 0 (all real)
            float2 A1 = sa[1], B1 = sb[1];
            sa[1] = make_float2(A1.x * B1.x, A1.y * B1.y);    // bin NF/2 (all real)
        } else {
            int p = __brev((unsigned)k) >> (32 - LOG2NF);
            int q = __brev((unsigned)(NF - k)) >> (32 - LOG2NF);
            float2 A = sa[p], Ac = sa[q];
            float2 Bv = sb[p], Bc = sb[q];
            float Xr  = 0.5f * (A.x + Ac.x),  Xi  = 0.5f * (A.y - Ac.y);
            float Xpr = 0.5f * (A.y + Ac.y),  Xpi = 0.5f * (Ac.x - A.x);
            float Fr  = 0.5f * (Bv.x + Bc.x), Fi  = 0.5f * (Bv.y - Bc.y);
            float Fpr = 0.5f * (Bv.y + Bc.y), Fpi = 0.5f * (Bc.x - Bv.x);
            float Yr  = Xr * Fr - Xi * Fi,    Yi  = Xr * Fi + Xi * Fr;
            float Ypr = Xpr * Fpr - Xpi * Fpi, Ypi = Xpr * Fpi + Xpi * Fpr;
            sa[p] = make_float2(Yr - Ypi, Yi + Ypr);          // G[k]    = Y + iY'
            sa[q] = make_float2(Yr + Ypi, Ypr - Yi);          // G[NF-k] = conj(Y) + i conj(Y')
        }
    }
    __syncthreads();

    // inverse DIT (conj twiddles), bit-reversed in -> natural out, unnormalized
    for (int m = 2; m <= NF; m <<= 1) {
        int half = m >> 1;
        int tstep = NF / m;
        for (int i = t; i < NF / 2; i += blockDim.x) {
            int j = i & (half - 1);
            int p = 2 * i - j;
            int q = p + half;
            float2 a = sa[p], bb = sa[q];
            float2 w = tw[j * tstep];
            float tx_ = bb.x * w.x + bb.y * w.y;   // bb * conj(w)
            float ty_ = bb.y * w.x - bb.x * w.y;
            sa[p] = make_float2(a.x + tx_, a.y + ty_);
            sa[q] = make_float2(a.x - tx_, a.y - ty_);
        }
        __syncthreads();
    }

    const float scale = 1.0f / (8192.0f * 8192.0f);
    for (int s = t; s < SS; s += blockDim.x) {
        float2 r = sa[s];
        op[s]      = zp[s]      * (r.x * scale);
        op[SS + s] = zp[SS + s] * (r.y * scale);
    }
}

// transpose v[b][d][s] -> vT[b*SS+s][d]
__global__ void vtrans_kernel() {
    __shared__ float tile[32][33];
    int tx = threadIdx.x & 31, ty = threadIdx.x >> 5;   // 32 x 8
    int s0 = blockIdx.x * 32;
    int d0 = blockIdx.y * 32;
    int b = blockIdx.z;
    #pragma unroll
    for (int r = 0; r < 4; r++) {
        int d = d0 + ty + r * 8;
        tile[ty + r * 8][tx] = g_v[(size_t)(b * 256 + d) * SS + s0 + tx];
    }
    __syncthreads();
    #pragma unroll
    for (int r = 0; r < 4; r++) {
        int s = s0 + ty + r * 8;
        g_vT[(size_t)(b * SS + s) * 256 + d0 + tx] = tile[tx][ty + r * 8];
    }
}

// ---------------- launch ----------------
extern "C" void kernel_launch(void* const* d_in, const int* in_sizes, int n_in,
                              void* d_out, int out_size) {
    const float* emb   = (const float*)d_in[0];
    const int*   pos   = (const int*)d_in[1];
    const float* Wproj = (const float*)d_in[2];
    const float* convw = (const float*)d_in[3];
    const float* convb = (const float*)d_in[4];
    const float* W1    = (const float*)d_in[5];
    const float* b1    = (const float*)d_in[6];
    const float* lng   = (const float*)d_in[7];
    const float* lnb   = (const float*)d_in[8];
    const float* W2    = (const float*)d_in[9];
    const float* b2    = (const float*)d_in[10];
    const float* ffs   = (const float*)d_in[11];
    const float* Wout  = (const float*)d_in[12];
    const float* bout  = (const float*)d_in[13];
    float* out = (float*)d_out;

    cudaFuncSetAttribute(fftconv2_kernel, cudaFuncAttributeMaxDynamicSharedMemorySize, 163840);

    tw_init_kernel<<<16, 256>>>();
    minpos_kernel<<<BB, 256>>>(pos);
    cwt_kernel<<<(3 * 256 * 768 + 255) / 256, 256>>>(convw);
    wc_gemm<<<dim3(12, 4, 3), 256>>>(Wproj);
    rope_kernel<<<BB * SS, 128>>>(emb, pos);
    zconv_mma<<<dim3(12, 256), 256>>>(emb, convb, pos);
    ffn_mma<256, false, false><<<dim3(4, 256), 256>>>(0, W1, b1, nullptr, nullptr, nullptr);
    ln_gelu_kernel<<<BB * SS, 256>>>(lng, lnb);
    ffn_mma<512, true, false><<<dim3(8, 256), 256>>>(1, W2, b2, ffs, nullptr, nullptr);
    hhat_kernel<<<BB * SS, 256>>>();
    fftconv2_kernel<<<BB * DD / 2, 512, 163840>>>(0);
    fftconv2_kernel<<<BB * DD / 2, 512, 163840>>>(1);
    vtrans_kernel<<<dim3(128, 8, 8), 256>>>();
    ffn_mma<256, false, true><<<dim3(4, 256), 256>>>(2, Wout, bout, nullptr, pos, out);
}

// round 7
// speedup vs baseline: 3.5637x; 1.2916x over previous
#include <cuda_runtime.h>
#include <math.h>
#include <stdint.h>

// Problem constants
#define BB 8
#define SS 4096
#define DD 256
#define GG 3
#define NORD 2
#define NF 8192          // FFT length = 2*S
#define LOG2NF 13

// ---------------- device scratch (static, no allocation) ----------------
__device__ float  g_minpos[BB];
__device__ float2 g_tw[NF/4];                      // twiddles e^{-2pi i k / NF}, k < NF/4
__device__ float  g_Wc[3 * 256 * 768];             // [tap*256+d][c] folded proj*conv weights
__device__ float  g_z[BB * GG * DD * SS];          // [b][g][d][s]  masked conv output
__device__ float  g_t[BB * SS * DD];               // rope output, later LN+gelu output
__device__ float  g_h1[BB * SS * DD];              // GEMM1 output
__device__ float  g_hh[BB * SS * 2 * DD];          // GEMM2 output
__device__ float  g_hsum[BB * SS * 2];             // per-row L1 sums of hh
__device__ float  g_h[NORD * BB * DD * SS];        // [n][b][d][s] normalized filters
__device__ float  g_v[BB * DD * SS];               // [b][d][s] final v
__device__ float  g_vT[BB * SS * DD];              // [b][s][d] transposed v for out gemm

// ---------------- helpers ----------------
__device__ __forceinline__ uint32_t sptr(const void* p) {
    return (uint32_t)__cvta_generic_to_shared(p);
}
__device__ __forceinline__ void cpa16(uint32_t dst, const void* src, int sz) {
    asm volatile("cp.async.ca.shared.global [%0], [%1], 16, %2;\n"
                 :: "r"(dst), "l"(src), "r"(sz));
}
__device__ __forceinline__ void cpa_commit() {
    asm volatile("cp.async.commit_group;\n" ::: "memory");
}
__device__ __forceinline__ void cpa_wait1() {
    asm volatile("cp.async.wait_group 1;\n" ::: "memory");
}
__device__ __forceinline__ void cpa_wait0() {
    asm volatile("cp.async.wait_group 0;\n" ::: "memory");
}
__device__ __forceinline__ void tf32_split(float v, uint32_t &h, uint32_t &l) {
    float hf;
    asm("cvt.rna.tf32.f32 %0, %1;" : "=f"(hf) : "f"(v));
    h = __float_as_uint(hf);
    l = __float_as_uint(v - hf);
}
__device__ __forceinline__ void mma8(float c[4], const uint32_t a[4], const uint32_t b[2]) {
    asm volatile(
        "mma.sync.aligned.m16n8k8.row.col.f32.tf32.tf32.f32 "
        "{%0,%1,%2,%3}, {%4,%5,%6,%7}, {%8,%9}, {%0,%1,%2,%3};\n"
        : "+f"(c[0]), "+f"(c[1]), "+f"(c[2]), "+f"(c[3])
        : "r"(a[0]), "r"(a[1]), "r"(a[2]), "r"(a[3]), "r"(b[0]), "r"(b[1]));
}
__device__ __forceinline__ float2 cmul(float2 a, float2 b) {
    return make_float2(a.x * b.x - a.y * b.y, a.x * b.y + a.y * b.x);
}
__device__ __forceinline__ float2 cmulc(float2 a, float2 w) {  // a * conj(w)
    return make_float2(a.x * w.x + a.y * w.y, a.y * w.x - a.x * w.y);
}
__device__ __forceinline__ float2 cadd(float2 a, float2 b) { return make_float2(a.x + b.x, a.y + b.y); }
__device__ __forceinline__ float2 csub(float2 a, float2 b) { return make_float2(a.x - b.x, a.y - b.y); }

// Compute one BK=16 slab: warp tile 32x32, 3-pass tf32 (err ~1e-6)
__device__ __forceinline__ void compute_slab16(
    const float (*As)[20], const float (*Bs)[72],
    int wm, int wn, int g, int tig, float acc[2][4][4])
{
    #pragma unroll
    for (int kb = 0; kb < 16; kb += 8) {
        uint32_t ah[2][4], al[2][4];
        #pragma unroll
        for (int mt = 0; mt < 2; mt++) {
            int rm = wm * 32 + mt * 16;
            tf32_split(As[rm + g][kb + tig],         ah[mt][0], al[mt][0]);
            tf32_split(As[rm + g + 8][kb + tig],     ah[mt][1], al[mt][1]);
            tf32_split(As[rm + g][kb + tig + 4],     ah[mt][2], al[mt][2]);
            tf32_split(As[rm + g + 8][kb + tig + 4], ah[mt][3], al[mt][3]);
        }
        uint32_t bh[4][2], bl[4][2];
        #pragma unroll
        for (int nt = 0; nt < 4; nt++) {
            int cn = wn * 32 + nt * 8 + g;
            tf32_split(Bs[kb + tig][cn],     bh[nt][0], bl[nt][0]);
            tf32_split(Bs[kb + tig + 4][cn], bh[nt][1], bl[nt][1]);
        }
        #pragma unroll
        for (int mt = 0; mt < 2; mt++)
            #pragma unroll
            for (int nt = 0; nt < 4; nt++) {
                mma8(acc[mt][nt], ah[mt], bh[nt]);
                mma8(acc[mt][nt], ah[mt], bl[nt]);
                mma8(acc[mt][nt], al[mt], bh[nt]);
            }
    }
}

// ---------------- init kernels ----------------
__global__ void tw_init_kernel() {
    int k = blockIdx.x * blockDim.x + threadIdx.x;
    if (k < NF/4) {
        double a = -2.0 * 3.14159265358979323846 * (double)k / (double)NF;
        double s, c;
        sincos(a, &s, &c);
        g_tw[k] = make_float2((float)c, (float)s);
    }
}

__global__ void minpos_kernel(const int* __restrict__ pos) {
    int b = blockIdx.x;
    int t = threadIdx.x;
    int local = 0x7fffffff;
    for (int s = t; s < SS; s += blockDim.x) {
        int p = pos[b * SS + s];
        if (p != -1) local = min(local, p);
    }
    for (int o = 16; o > 0; o >>= 1) local = min(local, __shfl_down_sync(0xffffffffu, local, o));
    __shared__ int wmin[8];
    if ((t & 31) == 0) wmin[t >> 5] = local;
    __syncthreads();
    if (t == 0) {
        int m = wmin[0];
        for (int i = 1; i < (int)(blockDim.x >> 5); i++) m = min(m, wmin[i]);
        g_minpos[b] = (float)m;
    }
}

// ---------------- small SIMT gemm for Wc precompute (conv_w gathered in-loader) ----
#define GEMM_CORE()                                                        \
    __syncthreads();                                                       \
    _Pragma("unroll")                                                      \
    for (int kk = 0; kk < 16; kk++) {                                      \
        float4 af = *(const float4*)&As[kk][ty * 4];                       \
        float4 bf = *(const float4*)&Bs[kk][tx * 4];                       \
        float ar[4] = {af.x, af.y, af.z, af.w};                            \
        float br[4] = {bf.x, bf.y, bf.z, bf.w};                            \
        _Pragma("unroll")                                                  \
        for (int i = 0; i < 4; i++)                                        \
            _Pragma("unroll")                                              \
            for (int j = 0; j < 4; j++) acc[i][j] += ar[i] * br[j];        \
    }                                                                      \
    __syncthreads();

// Wc[(tap*256 + d)][c] = sum_i Wproj[d][g*256+i] * conv_w[c][i][tap],  g = c/256
__global__ void wc_gemm(const float* __restrict__ Wproj, const float* __restrict__ convw) {
    __shared__ __align__(16) float As[16][64];
    __shared__ __align__(16) float Bs[16][64];
    int t = threadIdx.x;
    int tx = t & 15, ty = t >> 4;
    int n0 = blockIdx.x * 64;         // c
    int m0 = blockIdx.y * 64;         // d
    int tap = blockIdx.z;
    int g = n0 >> 8;
    int am = t >> 2, akq = t & 3;
    int bk = t >> 4, bnq = t & 15;
    float acc[4][4] = {};
    for (int k0 = 0; k0 < 256; k0 += 16) {
        float4 av = *(const float4*)(Wproj + (size_t)(m0 + am) * 768 + g * 256 + k0 + akq * 4);
        As[akq * 4 + 0][am] = av.x;
        As[akq * 4 + 1][am] = av.y;
        As[akq * 4 + 2][am] = av.z;
        As[akq * 4 + 3][am] = av.w;
        int i = k0 + bk;
        int c = n0 + bnq * 4;
        #pragma unroll
        for (int e = 0; e < 4; e++)
            Bs[bk][bnq * 4 + e] = convw[(size_t)(c + e) * 768 + i * 3 + tap];
        GEMM_CORE()
    }
    #pragma unroll
    for (int i = 0; i < 4; i++) {
        int d = m0 + ty * 4 + i;
        float4 v = make_float4(acc[i][0], acc[i][1], acc[i][2], acc[i][3]);
        *(float4*)(g_Wc + (size_t)(tap * 256 + d) * 768 + n0 + tx * 4) = v;
    }
}

// ---------------- rope ----------------
__global__ void rope_kernel(const float* __restrict__ emb, const int* __restrict__ pos) {
    int row = blockIdx.x;            // b*S + s
    int i = threadIdx.x;             // pair index 0..127
    int b = row >> 12;
    float2 xv = *(const float2*)(emb + (size_t)row * 256 + 2 * i);
    float frac = (float)i * (1.0f / 128.0f);
    float theta = 1.0f / powf(10000.0f, frac);
    int p = pos[row];
    float adj = (p == -1) ? -1.0f : ((float)p - g_minpos[b]);
    float ang = adj * theta;
    float sn, cs;
    sincosf(ang, &sn, &cs);
    float2 r;
    r.x = xv.x * cs - xv.y * sn;
    r.y = xv.x * sn + xv.y * cs;
    *(float2*)(g_t + (size_t)row * 256 + 2 * i) = r;
}

// ---------------- MMA GEMM: zconv (folded proj∘conv, im2col A) ----------------
// C[s, c] = mask[s] * (conv_b[c] + sum_{kk<768} A[s][kk] * Wc[kk][c])
// A[s][tap*256+d] = emb[b, s+tap-1, d].  Epilogue staged through smem for
// coalesced per-channel writes to g_z[ch][s].
__global__ __launch_bounds__(256, 2) void zconv_mma(
    const float* __restrict__ emb, const float* __restrict__ convb,
    const int* __restrict__ pos)
{
    __shared__ __align__(16) float As[2][128][20];
    __shared__ __align__(16) float Bs[2][16][72];
    int t = threadIdx.x;
    int w = t >> 5, lane = t & 31, g = lane >> 2, tig = lane & 3;
    int wm = w & 3, wn = w >> 2;
    int n0 = blockIdx.x * 64;
    int by = blockIdx.y;
    int b = by >> 5;
    int s0 = (by & 31) * 128;
    float acc[2][4][4] = {};

    auto issue = [&](int slab, int stage) {
        int k0 = slab * 16;
        int tap = k0 >> 8;
        #pragma unroll
        for (int p = 0; p < 2; p++) {
            int idx = t + p * 256;
            int r = idx >> 2, q = idx & 3;
            int sp = s0 + r + tap - 1;
            int ok = (sp >= 0 && sp < SS);
            int spc = min(max(sp, 0), SS - 1);
            const float* src = emb + (size_t)(b * SS + spc) * 256 + (k0 & 255) + q * 4;
            cpa16(sptr(&As[stage][r][q * 4]), src, ok ? 16 : 0);
        }
        {
            int k = t >> 4, nq = t & 15;
            const float* src = g_Wc + (size_t)(k0 + k) * 768 + n0 + nq * 4;
            cpa16(sptr(&Bs[stage][k][nq * 4]), src, 16);
        }
        cpa_commit();
    };

    issue(0, 0);
    const int KS = 48;
    for (int j = 0; j < KS; j++) {
        int st = j & 1;
        if (j + 1 < KS) { issue(j + 1, st ^ 1); cpa_wait1(); }
        else cpa_wait0();
        __syncthreads();
        compute_slab16(As[st], Bs[st], wm, wn, g, tig, acc);
        __syncthreads();
    }

    // staged epilogue: two 64s x 64c halves through smem scratch
    float (*sc)[65] = reinterpret_cast<float(*)[65]>(&As[0][0][0]);
    #pragma unroll
    for (int hs = 0; hs < 2; hs++) {
        if ((wm >> 1) == hs) {
            #pragma unroll
            for (int mt = 0; mt < 2; mt++) {
                int sl = (wm & 1) * 32 + mt * 16 + g;
                #pragma unroll
                for (int nt = 0; nt < 4; nt++) {
                    int cl = wn * 32 + nt * 8 + 2 * tig;
                    sc[cl][sl]         = acc[mt][nt][0];
                    sc[cl + 1][sl]     = acc[mt][nt][1];
                    sc[cl][sl + 8]     = acc[mt][nt][2];
                    sc[cl + 1][sl + 8] = acc[mt][nt][3];
                }
            }
        }
        __syncthreads();
        {
            int cl = t >> 2;
            int sl0 = (t & 3) * 16;
            int c = n0 + cl;
            float bias = __ldg(convb + c);
            size_t ch = (size_t)((b * 3 + (c >> 8)) * 256 + (c & 255)) * SS;
            int sbase = s0 + hs * 64 + sl0;
            #pragma unroll
            for (int e4 = 0; e4 < 4; e4++) {
                int s = sbase + e4 * 4;
                float4 v;
                v.x = (sc[cl][sl0 + e4 * 4 + 0] + bias) * ((pos[b * SS + s + 0] != -1) ? 1.f : 0.f);
                v.y = (sc[cl][sl0 + e4 * 4 + 1] + bias) * ((pos[b * SS + s + 1] != -1) ? 1.f : 0.f);
                v.z = (sc[cl][sl0 + e4 * 4 + 2] + bias) * ((pos[b * SS + s + 2] != -1) ? 1.f : 0.f);
                v.w = (sc[cl][sl0 + e4 * 4 + 3] + bias) * ((pos[b * SS + s + 3] != -1) ? 1.f : 0.f);
                *(float4*)(g_z + ch + s) = v;
            }
        }
        __syncthreads();
    }
}

// ---------------- MMA GEMM: generic row-major (ffn1, ffn2, out) ----------------
// sel=0: A=g_t,  C=g_h1  (LDN=256)
// sel=1: A=g_t,  C=g_hh  (LDN=512, scale)
// sel=2: A=g_vT, C=Cout  (LDN=256, mask)
template<int LDN, bool SCALE, bool MASK>
__global__ __launch_bounds__(256, 2) void ffn_mma(
    int sel, const float* __restrict__ B,
    const float* __restrict__ bias, const float* __restrict__ scale,
    const int* __restrict__ pos, float* __restrict__ Cout)
{
    const float* A = (sel == 2) ? g_vT : g_t;
    float* C = (sel == 0) ? g_h1 : (sel == 1) ? g_hh : Cout;

    __shared__ float As[2][128][20];
    __shared__ float Bs[2][16][72];
    int t = threadIdx.x;
    int w = t >> 5, lane = t & 31, g = lane >> 2, tig = lane & 3;
    int wm = w & 3, wn = w >> 2;
    int n0 = blockIdx.x * 64;
    int r0 = blockIdx.y * 128;
    float acc[2][4][4] = {};

    auto issue = [&](int slab, int stage) {
        int k0 = slab * 16;
        #pragma unroll
        for (int p = 0; p < 2; p++) {
            int idx = t + p * 256;
            int r = idx >> 2, q = idx & 3;
            cpa16(sptr(&As[stage][r][q * 4]), A + (size_t)(r0 + r) * 256 + k0 + q * 4, 16);
        }
        {
            int k = t >> 4, nq = t & 15;
            cpa16(sptr(&Bs[stage][k][nq * 4]), B + (size_t)(k0 + k) * LDN + n0 + nq * 4, 16);
        }
        cpa_commit();
    };

    issue(0, 0);
    const int KS = 16;
    for (int j = 0; j < KS; j++) {
        int st = j & 1;
        if (j + 1 < KS) { issue(j + 1, st ^ 1); cpa_wait1(); }
        else cpa_wait0();
        __syncthreads();
        compute_slab16(As[st], Bs[st], wm, wn, g, tig, acc);
        __syncthreads();
    }

    #pragma unroll
    for (int mt = 0; mt < 2; mt++) {
        int ra = r0 + wm * 32 + mt * 16 + g;
        int rb = ra + 8;
        float ma = 1.f, mb = 1.f;
        if (MASK) {
            ma = (pos[ra] != -1) ? 1.f : 0.f;
            mb = (pos[rb] != -1) ? 1.f : 0.f;
        }
        #pragma unroll
        for (int nt = 0; nt < 4; nt++) {
            int cn = n0 + wn * 32 + nt * 8 + 2 * tig;
            float2 bi = *(const float2*)(bias + cn);
            float sx = 1.f, sy = 1.f;
            if (SCALE) {
                float2 sc2 = *(const float2*)(scale + cn);
                sx = sc2.x; sy = sc2.y;
            }
            float2 va, vb;
            va.x = (acc[mt][nt][0] + bi.x) * sx * ma;
            va.y = (acc[mt][nt][1] + bi.y) * sy * ma;
            vb.x = (acc[mt][nt][2] + bi.x) * sx * mb;
            vb.y = (acc[mt][nt][3] + bi.y) * sy * mb;
            *(float2*)(C + (size_t)ra * LDN + cn) = va;
            *(float2*)(C + (size_t)rb * LDN + cn) = vb;
        }
    }
}

// LayerNorm (two-pass) + exact gelu: reads g_h1, writes g_t
__global__ void ln_gelu_kernel(const float* __restrict__ lng, const float* __restrict__ lnb) {
    int row = blockIdx.x;
    int t = threadIdx.x;
    float v = g_h1[(size_t)row * 256 + t];
    __shared__ float ws[8];
    float s1 = v;
    for (int o = 16; o > 0; o >>= 1) s1 += __shfl_down_sync(0xffffffffu, s1, o);
    if ((t & 31) == 0) ws[t >> 5] = s1;
    __syncthreads();
    if (t == 0) {
        float a = 0.f;
        for (int i = 0; i < 8; i++) a += ws[i];
        ws[0] = a;
    }
    __syncthreads();
    float mu = ws[0] * (1.f / 256.f);
    __syncthreads();
    float dv = v - mu;
    float s2 = dv * dv;
    for (int o = 16; o > 0; o >>= 1) s2 += __shfl_down_sync(0xffffffffu, s2, o);
    if ((t & 31) == 0) ws[t >> 5] = s2;
    __syncthreads();
    if (t == 0) {
        float a = 0.f;
        for (int i = 0; i < 8; i++) a += ws[i];
        ws[0] = a;
    }
    __syncthreads();
    float var = ws[0] * (1.f / 256.f);
    float xn = dv / sqrtf(var + 1e-5f) * lng[t] + lnb[t];
    float ge = 0.5f * xn * (1.f + erff(xn / sqrtf(2.0f)));
    g_t[(size_t)row * 256 + t] = ge;
}

// per-row L1 sums of g_hh (both n), coalesced
__global__ void hsum_kernel() {
    int row = blockIdx.x;
    int t = threadIdx.x;
    float a0 = fabsf(g_hh[(size_t)row * 512 + t]);
    float a1 = fabsf(g_hh[(size_t)row * 512 + 256 + t]);
    for (int o = 16; o > 0; o >>= 1) {
        a0 += __shfl_down_sync(0xffffffffu, a0, o);
        a1 += __shfl_down_sync(0xffffffffu, a1, o);
    }
    __shared__ float w0[8], w1[8];
    if ((t & 31) == 0) { w0[t >> 5] = a0; w1[t >> 5] = a1; }
    __syncthreads();
    if (t == 0) {
        float s0 = 0.f, s1 = 0.f;
        for (int i = 0; i < 8; i++) { s0 += w0[i]; s1 += w1[i]; }
        g_hsum[row * 2 + 0] = s0;
        g_hsum[row * 2 + 1] = s1;
    }
}

// normalize + tiled transpose: g_h[n][b][d][s] = hh[b*S+s][n*256+d] / (sum + 1e-8)
__global__ void htrans_kernel() {
    __shared__ float tile[32][33];
    int tx = threadIdx.x & 31, ty = threadIdx.x >> 5;   // 32 x 8
    int s0 = blockIdx.x * 32;
    int d0 = blockIdx.y * 32;
    int bz = blockIdx.z;
    int b = bz >> 1, n = bz & 1;
    #pragma unroll
    for (int r = 0; r < 4; r++) {
        int s = s0 + ty + r * 8;
        float den = g_hsum[(size_t)(b * SS + s) * 2 + n] + 1e-8f;
        tile[ty + r * 8][tx] = g_hh[(size_t)(b * SS + s) * 512 + n * 256 + d0 + tx] / den;
    }
    __syncthreads();
    #pragma unroll
    for (int r = 0; r < 4; r++) {
        int d = d0 + ty + r * 8;
        g_h[((size_t)(n * BB + b) * 256 + d) * SS + s0 + tx] = tile[tx][ty + r * 8];
    }
}

// ---------------- fused FFT causal conv, channel-pair packing, radix-2^2 ----------------
// One block per channel PAIR (d0, d0+1); BOTH conv iterations in-block (v stays in smem).
// Forward: 6 combined radix-2^2 DIF passes + 1 twiddle-free radix-2 stage (bit-reversed out,
// ordering bit-identical to plain radix-2 DIF). Hermitian split product. Inverse: twiddle-free
// radix-2 stage + 6 combined radix-2^2 DIT passes (natural out).
__global__ __launch_bounds__(1024, 1) void fftconv_fused() {
    extern __shared__ float2 smbuf[];
    float2* sa = smbuf;            // NF complex (x pair)
    float2* sb = smbuf + NF;       // NF complex (f pair)
    float2* tw = smbuf + 2 * NF;   // NF/4 twiddles
    int t = threadIdx.x;
    int pi = blockIdx.x;           // 0..1023
    int b = pi >> 7;
    int d0 = (pi & 127) * 2;
    const float* xp0 = g_z + (size_t)((b * 3 + 2) * 256 + d0) * SS;
    float* op = g_v + (size_t)(b * 256 + d0) * SS;

    for (int i = t; i < NF / 4; i += 1024) tw[i] = g_tw[i];
    for (int s = t; s < SS; s += 1024) sa[s] = make_float2(xp0[s], xp0[SS + s]);
    for (int s = SS + t; s < NF; s += 1024) sa[s] = make_float2(0.f, 0.f);

    #pragma unroll 1
    for (int iter = 0; iter < 2; iter++) {
        const float* fp = g_h + (size_t)iter * (BB * DD * SS) + (size_t)(b * 256 + d0) * SS;
        const float* zp = g_z + (size_t)((b * 3 + iter) * 256 + d0) * SS;
        for (int s = t; s < SS; s += 1024) sb[s] = make_float2(fp[s], fp[SS + s]);
        for (int s = SS + t; s < NF; s += 1024) sb[s] = make_float2(0.f, 0.f);
        __syncthreads();

        // forward: 6 radix-2^2 passes (halves H & H/2), H = 4096..4
        #pragma unroll 1
        for (int lg = 11; lg >= 1; lg -= 2) {
            int hh = 1 << lg;          // H/2
            int H = hh << 1;
            int ts1 = 1 << (11 - lg);  // NF/(2H)
            for (int u = t; u < NF / 4; u += 1024) {
                int j0 = u & (hh - 1);
                int p0 = ((u >> lg) << (lg + 2)) + j0;
                float2 w1 = tw[j0 * ts1];
                float2 w1b = make_float2(w1.y, -w1.x);
                float2 w2 = cmul(w1, w1);
                {
                    float2 a0 = sa[p0], a1 = sa[p0 + hh], a2 = sa[p0 + H], a3 = sa[p0 + H + hh];
                    float2 t0 = cadd(a0, a2), u2 = cmul(csub(a0, a2), w1);
                    float2 t1 = cadd(a1, a3), u3 = cmul(csub(a1, a3), w1b);
                    sa[p0]          = cadd(t0, t1);
                    sa[p0 + hh]     = cmul(csub(t0, t1), w2);
                    sa[p0 + H]      = cadd(u2, u3);
                    sa[p0 + H + hh] = cmul(csub(u2, u3), w2);
                }
                {
                    float2 a0 = sb[p0], a1 = sb[p0 + hh], a2 = sb[p0 + H], a3 = sb[p0 + H + hh];
                    float2 t0 = cadd(a0, a2), u2 = cmul(csub(a0, a2), w1);
                    float2 t1 = cadd(a1, a3), u3 = cmul(csub(a1, a3), w1b);
                    sb[p0]          = cadd(t0, t1);
                    sb[p0 + hh]     = cmul(csub(t0, t1), w2);
                    sb[p0 + H]      = cadd(u2, u3);
                    sb[p0 + H + hh] = cmul(csub(u2, u3), w2);
                }
            }
            __syncthreads();
        }
        // final forward radix-2 stage (half=1, w=1)
        for (int i = t; i < NF / 2; i += 1024) {
            int p = 2 * i;
            float2 a = sa[p], bq = sa[p + 1];
            sa[p] = cadd(a, bq); sa[p + 1] = csub(a, bq);
            float2 c = sb[p], dq = sb[p + 1];
            sb[p] = cadd(c, dq); sb[p + 1] = csub(c, dq);
        }
        __syncthreads();

        // per-channel spectral product in bit-reversed domain, result packed into sa
        for (int k = t; k < NF / 2; k += 1024) {
            if (k == 0) {
                float2 A0 = sa[0], B0 = sb[0];
                sa[0] = make_float2(A0.x * B0.x, A0.y * B0.y);    // bin 0
                float2 A1 = sa[1], B1 = sb[1];
                sa[1] = make_float2(A1.x * B1.x, A1.y * B1.y);    // bin NF/2
            } else {
                int p = __brev((unsigned)k) >> (32 - LOG2NF);
                int q = __brev((unsigned)(NF - k)) >> (32 - LOG2NF);
                float2 A = sa[p], Ac = sa[q];
                float2 Bv = sb[p], Bc = sb[q];
                float Xr  = 0.5f * (A.x + Ac.x),  Xi  = 0.5f * (A.y - Ac.y);
                float Xpr = 0.5f * (A.y + Ac.y),  Xpi = 0.5f * (Ac.x - A.x);
                float Fr  = 0.5f * (Bv.x + Bc.x), Fi  = 0.5f * (Bv.y - Bc.y);
                float Fpr = 0.5f * (Bv.y + Bc.y), Fpi = 0.5f * (Bc.x - Bv.x);
                float Yr  = Xr * Fr - Xi * Fi,     Yi  = Xr * Fi + Xi * Fr;
                float Ypr = Xpr * Fpr - Xpi * Fpi, Ypi = Xpr * Fpi + Xpi * Fpr;
                sa[p] = make_float2(Yr - Ypi, Yi + Ypr);
                sa[q] = make_float2(Yr + Ypi, Ypr - Yi);
            }
        }
        __syncthreads();

        // inverse: first radix-2 stage (m=2, w=1)
        for (int i = t; i < NF / 2; i += 1024) {
            int p = 2 * i;
            float2 a = sa[p], bq = sa[p + 1];
            sa[p] = cadd(a, bq); sa[p + 1] = csub(a, bq);
        }
        __syncthreads();
        // 6 radix-2^2 DIT passes, m = 4..4096 (stages m and 2m), conj twiddles
        #pragma unroll 1
        for (int lgm = 2; lgm <= 12; lgm += 2) {
            int m = 1 << lgm;
            int hm = m >> 1;
            int ts = NF >> (lgm + 1);   // NF/(2m)
            for (int u = t; u < NF / 4; u += 1024) {
                int j0 = u & (hm - 1);
                int i0 = ((u >> (lgm - 1)) << (lgm + 1)) + j0;
                float2 wb = tw[j0 * ts];
                float2 wm = cmul(wb, wb);
                float2 a0 = sa[i0], a1 = sa[i0 + hm], a2 = sa[i0 + m], a3 = sa[i0 + m + hm];
                float2 t1 = cmulc(a1, wm);
                float2 o0 = cadd(a0, t1), o1 = csub(a0, t1);
                float2 t3 = cmulc(a3, wm);
                float2 o2 = cadd(a2, t3), o3 = csub(a2, t3);
                float2 c2 = cmulc(o2, wb);
                float2 cz = cmulc(o3, wb);
                float2 t2 = make_float2(-cz.y, cz.x);   // i * cz
                sa[i0]          = cadd(o0, c2);
                sa[i0 + m]      = csub(o0, c2);
                sa[i0 + hm]     = cadd(o1, t2);
                sa[i0 + m + hm] = csub(o1, t2);
            }
            __syncthreads();
        }

        const float scale = 1.0f / (8192.0f * 8192.0f);
        if (iter == 0) {
            // v = z0 * conv; becomes x for iter 1, kept in smem
            for (int s = t; s < SS; s += 1024) {
                float2 r = sa[s];
                sa[s] = make_float2(zp[s] * (r.x * scale), zp[SS + s] * (r.y * scale));
            }
            for (int s = SS + t; s < NF; s += 1024) sa[s] = make_float2(0.f, 0.f);
        } else {
            for (int s = t; s < SS; s += 1024) {
                float2 r = sa[s];
                op[s]      = zp[s]      * (r.x * scale);
                op[SS + s] = zp[SS + s] * (r.y * scale);
            }
        }
    }
}

// transpose v[b][d][s] -> vT[b*SS+s][d]
__global__ void vtrans_kernel() {
    __shared__ float tile[32][33];
    int tx = threadIdx.x & 31, ty = threadIdx.x >> 5;   // 32 x 8
    int s0 = blockIdx.x * 32;
    int d0 = blockIdx.y * 32;
    int b = blockIdx.z;
    #pragma unroll
    for (int r = 0; r < 4; r++) {
        int d = d0 + ty + r * 8;
        tile[ty + r * 8][tx] = g_v[(size_t)(b * 256 + d) * SS + s0 + tx];
    }
    __syncthreads();
    #pragma unroll
    for (int r = 0; r < 4; r++) {
        int s = s0 + ty + r * 8;
        g_vT[(size_t)(b * SS + s) * 256 + d0 + tx] = tile[tx][ty + r * 8];
    }
}

// ---------------- launch ----------------
extern "C" void kernel_launch(void* const* d_in, const int* in_sizes, int n_in,
                              void* d_out, int out_size) {
    const float* emb   = (const float*)d_in[0];
    const int*   pos   = (const int*)d_in[1];
    const float* Wproj = (const float*)d_in[2];
    const float* convw = (const float*)d_in[3];
    const float* convb = (const float*)d_in[4];
    const float* W1    = (const float*)d_in[5];
    const float* b1    = (const float*)d_in[6];
    const float* lng   = (const float*)d_in[7];
    const float* lnb   = (const float*)d_in[8];
    const float* W2    = (const float*)d_in[9];
    const float* b2    = (const float*)d_in[10];
    const float* ffs   = (const float*)d_in[11];
    const float* Wout  = (const float*)d_in[12];
    const float* bout  = (const float*)d_in[13];
    float* out = (float*)d_out;

    cudaFuncSetAttribute(fftconv_fused, cudaFuncAttributeMaxDynamicSharedMemorySize, 147456);

    tw_init_kernel<<<8, 256>>>();
    minpos_kernel<<<BB, 256>>>(pos);
    wc_gemm<<<dim3(12, 4, 3), 256>>>(Wproj, convw);
    rope_kernel<<<BB * SS, 128>>>(emb, pos);
    zconv_mma<<<dim3(12, 256), 256>>>(emb, convb, pos);
    ffn_mma<256, false, false><<<dim3(4, 256), 256>>>(0, W1, b1, nullptr, nullptr, nullptr);
    ln_gelu_kernel<<<BB * SS, 256>>>(lng, lnb);
    ffn_mma<512, true, false><<<dim3(8, 256), 256>>>(1, W2, b2, ffs, nullptr, nullptr);
    hsum_kernel<<<BB * SS, 256>>>();
    htrans_kernel<<<dim3(128, 8, 16), 256>>>();
    fftconv_fused<<<BB * DD / 2, 1024, 147456>>>();
    vtrans_kernel<<<dim3(128, 8, 8), 256>>>();
    ffn_mma<256, false, true><<<dim3(4, 256), 256>>>(2, Wout, bout, nullptr, pos, out);
}

// round 9
// speedup vs baseline: 3.8805x; 1.0889x over previous
#include <cuda_runtime.h>
#include <math.h>
#include <stdint.h>

// Problem constants
#define BB 8
#define SS 4096
#define DD 256
#define GG 3
#define NORD 2
#define NF 8192          // FFT length = 2*S
#define LOG2NF 13

// padded smem index: 1 extra float2 per 16 -> kills power-of-2-stride bank conflicts
#define FIDX(i) ((i) + ((i) >> 4))
#define SA_PAD 8704      // FIDX(8191)+1 = 8191+511+1+1 -> 8704
#define TW_PAD 2176      // FIDX(2047)+1 -> 2175+1 = 2176

// ---------------- device scratch (static, no allocation) ----------------
__device__ float  g_minpos[BB];
__device__ float  g_theta[128];
__device__ float2 g_tw[NF/4];                      // twiddles e^{-2pi i k / NF}, k < NF/4
__device__ float  g_Wc[3 * 256 * 768];             // [tap*256+d][c] folded proj*conv weights
__device__ float  g_z[BB * GG * DD * SS];          // [b][g][d][s]  masked conv output
__device__ float  g_t[BB * SS * DD];               // rope output, later LN+gelu output
__device__ float  g_h1[BB * SS * DD];              // GEMM1 output
__device__ float  g_hh[BB * SS * 2 * DD];          // GEMM2 output
__device__ float  g_h[NORD * BB * DD * SS];        // [n][b][d][s] normalized filters
__device__ float  g_v[BB * DD * SS];               // [b][d][s] final v
__device__ float  g_vT[BB * SS * DD];              // [b][s][d] transposed v for out gemm

// ---------------- helpers ----------------
__device__ __forceinline__ uint32_t sptr(const void* p) {
    return (uint32_t)__cvta_generic_to_shared(p);
}
__device__ __forceinline__ void cpa16(uint32_t dst, const void* src, int sz) {
    asm volatile("cp.async.ca.shared.global [%0], [%1], 16, %2;\n"
                 :: "r"(dst), "l"(src), "r"(sz));
}
__device__ __forceinline__ void cpa_commit() {
    asm volatile("cp.async.commit_group;\n" ::: "memory");
}
__device__ __forceinline__ void cpa_wait1() {
    asm volatile("cp.async.wait_group 1;\n" ::: "memory");
}
__device__ __forceinline__ void cpa_wait0() {
    asm volatile("cp.async.wait_group 0;\n" ::: "memory");
}
__device__ __forceinline__ void tf32_split(float v, uint32_t &h, uint32_t &l) {
    float hf;
    asm("cvt.rna.tf32.f32 %0, %1;" : "=f"(hf) : "f"(v));
    h = __float_as_uint(hf);
    l = __float_as_uint(v - hf);
}
__device__ __forceinline__ void mma8(float c[4], const uint32_t a[4], const uint32_t b[2]) {
    asm volatile(
        "mma.sync.aligned.m16n8k8.row.col.f32.tf32.tf32.f32 "
        "{%0,%1,%2,%3}, {%4,%5,%6,%7}, {%8,%9}, {%0,%1,%2,%3};\n"
        : "+f"(c[0]), "+f"(c[1]), "+f"(c[2]), "+f"(c[3])
        : "r"(a[0]), "r"(a[1]), "r"(a[2]), "r"(a[3]), "r"(b[0]), "r"(b[1]));
}
__device__ __forceinline__ float2 cmul(float2 a, float2 b) {
    return make_float2(a.x * b.x - a.y * b.y, a.x * b.y + a.y * b.x);
}
__device__ __forceinline__ float2 cmulc(float2 a, float2 w) {  // a * conj(w)
    return make_float2(a.x * w.x + a.y * w.y, a.y * w.x - a.x * w.y);
}
__device__ __forceinline__ float2 cadd(float2 a, float2 b) { return make_float2(a.x + b.x, a.y + b.y); }
__device__ __forceinline__ float2 csub(float2 a, float2 b) { return make_float2(a.x - b.x, a.y - b.y); }

// Compute one BK=16 slab: warp tile 32x32, 3-pass tf32 (err ~1e-6)
__device__ __forceinline__ void compute_slab16(
    const float (*As)[20], const float (*Bs)[72],
    int wm, int wn, int g, int tig, float acc[2][4][4])
{
    #pragma unroll
    for (int kb = 0; kb < 16; kb += 8) {
        uint32_t ah[2][4], al[2][4];
        #pragma unroll
        for (int mt = 0; mt < 2; mt++) {
            int rm = wm * 32 + mt * 16;
            tf32_split(As[rm + g][kb + tig],         ah[mt][0], al[mt][0]);
            tf32_split(As[rm + g + 8][kb + tig],     ah[mt][1], al[mt][1]);
            tf32_split(As[rm + g][kb + tig + 4],     ah[mt][2], al[mt][2]);
            tf32_split(As[rm + g + 8][kb + tig + 4], ah[mt][3], al[mt][3]);
        }
        uint32_t bh[4][2], bl[4][2];
        #pragma unroll
        for (int nt = 0; nt < 4; nt++) {
            int cn = wn * 32 + nt * 8 + g;
            tf32_split(Bs[kb + tig][cn],     bh[nt][0], bl[nt][0]);
            tf32_split(Bs[kb + tig + 4][cn], bh[nt][1], bl[nt][1]);
        }
        #pragma unroll
        for (int mt = 0; mt < 2; mt++)
            #pragma unroll
            for (int nt = 0; nt < 4; nt++) {
                mma8(acc[mt][nt], ah[mt], bh[nt]);
                mma8(acc[mt][nt], ah[mt], bl[nt]);
                mma8(acc[mt][nt], al[mt], bh[nt]);
            }
    }
}

// ---------------- init kernels ----------------
__global__ void tw_init_kernel() {
    int k = blockIdx.x * blockDim.x + threadIdx.x;
    if (k < NF/4) {
        double a = -2.0 * 3.14159265358979323846 * (double)k / (double)NF;
        double s, c;
        sincos(a, &s, &c);
        g_tw[k] = make_float2((float)c, (float)s);
    }
    if (k < 128) {
        float frac = (float)k * (1.0f / 128.0f);
        g_theta[k] = 1.0f / powf(10000.0f, frac);
    }
}

__global__ void minpos_kernel(const int* __restrict__ pos) {
    int b = blockIdx.x;
    int t = threadIdx.x;
    int local = 0x7fffffff;
    for (int s = t; s < SS; s += blockDim.x) {
        int p = pos[b * SS + s];
        if (p != -1) local = min(local, p);
    }
    for (int o = 16; o > 0; o >>= 1) local = min(local, __shfl_down_sync(0xffffffffu, local, o));
    __shared__ int wmin[8];
    if ((t & 31) == 0) wmin[t >> 5] = local;
    __syncthreads();
    if (t == 0) {
        int m = wmin[0];
        for (int i = 1; i < (int)(blockDim.x >> 5); i++) m = min(m, wmin[i]);
        g_minpos[b] = (float)m;
    }
}

// ---------------- small SIMT gemm for Wc precompute (conv_w gathered in-loader) ----
#define GEMM_CORE()                                                        \
    __syncthreads();                                                       \
    _Pragma("unroll")                                                      \
    for (int kk = 0; kk < 16; kk++) {                                      \
        float4 af = *(const float4*)&As[kk][ty * 4];                       \
        float4 bf = *(const float4*)&Bs[kk][tx * 4];                       \
        float ar[4] = {af.x, af.y, af.z, af.w};                            \
        float br[4] = {bf.x, bf.y, bf.z, bf.w};                            \
        _Pragma("unroll")                                                  \
        for (int i = 0; i < 4; i++)                                        \
            _Pragma("unroll")                                              \
            for (int j = 0; j < 4; j++) acc[i][j] += ar[i] * br[j];        \
    }                                                                      \
    __syncthreads();

// Wc[(tap*256 + d)][c] = sum_i Wproj[d][g*256+i] * conv_w[c][i][tap],  g = c/256
__global__ void wc_gemm(const float* __restrict__ Wproj, const float* __restrict__ convw) {
    __shared__ __align__(16) float As[16][64];
    __shared__ __align__(16) float Bs[16][64];
    int t = threadIdx.x;
    int tx = t & 15, ty = t >> 4;
    int n0 = blockIdx.x * 64;         // c
    int m0 = blockIdx.y * 64;         // d
    int tap = blockIdx.z;
    int g = n0 >> 8;
    int am = t >> 2, akq = t & 3;
    int bk = t >> 4, bnq = t & 15;
    float acc[4][4] = {};
    for (int k0 = 0; k0 < 256; k0 += 16) {
        float4 av = *(const float4*)(Wproj + (size_t)(m0 + am) * 768 + g * 256 + k0 + akq * 4);
        As[akq * 4 + 0][am] = av.x;
        As[akq * 4 + 1][am] = av.y;
        As[akq * 4 + 2][am] = av.z;
        As[akq * 4 + 3][am] = av.w;
        int i = k0 + bk;
        int c = n0 + bnq * 4;
        #pragma unroll
        for (int e = 0; e < 4; e++)
            Bs[bk][bnq * 4 + e] = convw[(size_t)(c + e) * 768 + i * 3 + tap];
        GEMM_CORE()
    }
    #pragma unroll
    for (int i = 0; i < 4; i++) {
        int d = m0 + ty * 4 + i;
        float4 v = make_float4(acc[i][0], acc[i][1], acc[i][2], acc[i][3]);
        *(float4*)(g_Wc + (size_t)(tap * 256 + d) * 768 + n0 + tx * 4) = v;
    }
}

// ---------------- rope (theta from table) ----------------
__global__ void rope_kernel(const float* __restrict__ emb, const int* __restrict__ pos) {
    int row = blockIdx.x;            // b*S + s
    int i = threadIdx.x;             // pair index 0..127
    int b = row >> 12;
    float2 xv = *(const float2*)(emb + (size_t)row * 256 + 2 * i);
    float theta = g_theta[i];
    int p = pos[row];
    float adj = (p == -1) ? -1.0f : ((float)p - g_minpos[b]);
    float ang = adj * theta;
    float sn, cs;
    sincosf(ang, &sn, &cs);
    float2 r;
    r.x = xv.x * cs - xv.y * sn;
    r.y = xv.x * sn + xv.y * cs;
    *(float2*)(g_t + (size_t)row * 256 + 2 * i) = r;
}

// ---------------- MMA GEMM: zconv (folded proj∘conv, im2col A) ----------------
__global__ __launch_bounds__(256, 2) void zconv_mma(
    const float* __restrict__ emb, const float* __restrict__ convb,
    const int* __restrict__ pos)
{
    __shared__ __align__(16) float As[2][128][20];
    __shared__ __align__(16) float Bs[2][16][72];
    int t = threadIdx.x;
    int w = t >> 5, lane = t & 31, g = lane >> 2, tig = lane & 3;
    int wm = w & 3, wn = w >> 2;
    int n0 = blockIdx.x * 64;
    int by = blockIdx.y;
    int b = by >> 5;
    int s0 = (by & 31) * 128;
    float acc[2][4][4] = {};

    auto issue = [&](int slab, int stage) {
        int k0 = slab * 16;
        int tap = k0 >> 8;
        #pragma unroll
        for (int p = 0; p < 2; p++) {
            int idx = t + p * 256;
            int r = idx >> 2, q = idx & 3;
            int sp = s0 + r + tap - 1;
            int ok = (sp >= 0 && sp < SS);
            int spc = min(max(sp, 0), SS - 1);
            const float* src = emb + (size_t)(b * SS + spc) * 256 + (k0 & 255) + q * 4;
            cpa16(sptr(&As[stage][r][q * 4]), src, ok ? 16 : 0);
        }
        {
            int k = t >> 4, nq = t & 15;
            const float* src = g_Wc + (size_t)(k0 + k) * 768 + n0 + nq * 4;
            cpa16(sptr(&Bs[stage][k][nq * 4]), src, 16);
        }
        cpa_commit();
    };

    issue(0, 0);
    const int KS = 48;
    for (int j = 0; j < KS; j++) {
        int st = j & 1;
        if (j + 1 < KS) { issue(j + 1, st ^ 1); cpa_wait1(); }
        else cpa_wait0();
        __syncthreads();
        compute_slab16(As[st], Bs[st], wm, wn, g, tig, acc);
        __syncthreads();
    }

    // staged epilogue: two 64s x 64c halves through smem scratch
    float (*sc)[65] = reinterpret_cast<float(*)[65]>(&As[0][0][0]);
    #pragma unroll
    for (int hs = 0; hs < 2; hs++) {
        if ((wm >> 1) == hs) {
            #pragma unroll
            for (int mt = 0; mt < 2; mt++) {
                int sl = (wm & 1) * 32 + mt * 16 + g;
                #pragma unroll
                for (int nt = 0; nt < 4; nt++) {
                    int cl = wn * 32 + nt * 8 + 2 * tig;
                    sc[cl][sl]         = acc[mt][nt][0];
                    sc[cl + 1][sl]     = acc[mt][nt][1];
                    sc[cl][sl + 8]     = acc[mt][nt][2];
                    sc[cl + 1][sl + 8] = acc[mt][nt][3];
                }
            }
        }
        __syncthreads();
        {
            int cl = t >> 2;
            int sl0 = (t & 3) * 16;
            int c = n0 + cl;
            float bias = __ldg(convb + c);
            size_t ch = (size_t)((b * 3 + (c >> 8)) * 256 + (c & 255)) * SS;
            int sbase = s0 + hs * 64 + sl0;
            #pragma unroll
            for (int e4 = 0; e4 < 4; e4++) {
                int s = sbase + e4 * 4;
                float4 v;
                v.x = (sc[cl][sl0 + e4 * 4 + 0] + bias) * ((pos[b * SS + s + 0] != -1) ? 1.f : 0.f);
                v.y = (sc[cl][sl0 + e4 * 4 + 1] + bias) * ((pos[b * SS + s + 1] != -1) ? 1.f : 0.f);
                v.z = (sc[cl][sl0 + e4 * 4 + 2] + bias) * ((pos[b * SS + s + 2] != -1) ? 1.f : 0.f);
                v.w = (sc[cl][sl0 + e4 * 4 + 3] + bias) * ((pos[b * SS + s + 3] != -1) ? 1.f : 0.f);
                *(float4*)(g_z + ch + s) = v;
            }
        }
        __syncthreads();
    }
}

// ---------------- MMA GEMM: generic row-major (ffn1, ffn2, out) ----------------
// sel=0: A=g_t,  C=g_h1  (LDN=256)
// sel=1: A=g_t,  C=g_hh  (LDN=512, scale)
// sel=2: A=g_vT, C=Cout  (LDN=256, mask)
template<int LDN, bool SCALE, bool MASK>
__global__ __launch_bounds__(256, 2) void ffn_mma(
    int sel, const float* __restrict__ B,
    const float* __restrict__ bias, const float* __restrict__ scale,
    const int* __restrict__ pos, float* __restrict__ Cout)
{
    const float* A = (sel == 2) ? g_vT : g_t;
    float* C = (sel == 0) ? g_h1 : (sel == 1) ? g_hh : Cout;

    __shared__ float As[2][128][20];
    __shared__ float Bs[2][16][72];
    int t = threadIdx.x;
    int w = t >> 5, lane = t & 31, g = lane >> 2, tig = lane & 3;
    int wm = w & 3, wn = w >> 2;
    int n0 = blockIdx.x * 64;
    int r0 = blockIdx.y * 128;
    float acc[2][4][4] = {};

    auto issue = [&](int slab, int stage) {
        int k0 = slab * 16;
        #pragma unroll
        for (int p = 0; p < 2; p++) {
            int idx = t + p * 256;
            int r = idx >> 2, q = idx & 3;
            cpa16(sptr(&As[stage][r][q * 4]), A + (size_t)(r0 + r) * 256 + k0 + q * 4, 16);
        }
        {
            int k = t >> 4, nq = t & 15;
            cpa16(sptr(&Bs[stage][k][nq * 4]), B + (size_t)(k0 + k) * LDN + n0 + nq * 4, 16);
        }
        cpa_commit();
    };

    issue(0, 0);
    const int KS = 16;
    for (int j = 0; j < KS; j++) {
        int st = j & 1;
        if (j + 1 < KS) { issue(j + 1, st ^ 1); cpa_wait1(); }
        else cpa_wait0();
        __syncthreads();
        compute_slab16(As[st], Bs[st], wm, wn, g, tig, acc);
        __syncthreads();
    }

    #pragma unroll
    for (int mt = 0; mt < 2; mt++) {
        int ra = r0 + wm * 32 + mt * 16 + g;
        int rb = ra + 8;
        float ma = 1.f, mb = 1.f;
        if (MASK) {
            ma = (pos[ra] != -1) ? 1.f : 0.f;
            mb = (pos[rb] != -1) ? 1.f : 0.f;
        }
        #pragma unroll
        for (int nt = 0; nt < 4; nt++) {
            int cn = n0 + wn * 32 + nt * 8 + 2 * tig;
            float2 bi = *(const float2*)(bias + cn);
            float sx = 1.f, sy = 1.f;
            if (SCALE) {
                float2 sc2 = *(const float2*)(scale + cn);
                sx = sc2.x; sy = sc2.y;
            }
            float2 va, vb;
            va.x = (acc[mt][nt][0] + bi.x) * sx * ma;
            va.y = (acc[mt][nt][1] + bi.y) * sy * ma;
            vb.x = (acc[mt][nt][2] + bi.x) * sx * mb;
            vb.y = (acc[mt][nt][3] + bi.y) * sy * mb;
            *(float2*)(C + (size_t)ra * LDN + cn) = va;
            *(float2*)(C + (size_t)rb * LDN + cn) = vb;
        }
    }
}

// LayerNorm (two-pass) + exact gelu: reads g_h1, writes g_t
__global__ void ln_gelu_kernel(const float* __restrict__ lng, const float* __restrict__ lnb) {
    int row = blockIdx.x;
    int t = threadIdx.x;
    float v = g_h1[(size_t)row * 256 + t];
    __shared__ float ws[8];
    float s1 = v;
    for (int o = 16; o > 0; o >>= 1) s1 += __shfl_down_sync(0xffffffffu, s1, o);
    if ((t & 31) == 0) ws[t >> 5] = s1;
    __syncthreads();
    if (t == 0) {
        float a = 0.f;
        for (int i = 0; i < 8; i++) a += ws[i];
        ws[0] = a;
    }
    __syncthreads();
    float mu = ws[0] * (1.f / 256.f);
    __syncthreads();
    float dv = v - mu;
    float s2 = dv * dv;
    for (int o = 16; o > 0; o >>= 1) s2 += __shfl_down_sync(0xffffffffu, s2, o);
    if ((t & 31) == 0) ws[t >> 5] = s2;
    __syncthreads();
    if (t == 0) {
        float a = 0.f;
        for (int i = 0; i < 8; i++) a += ws[i];
        ws[0] = a;
    }
    __syncthreads();
    float var = ws[0] * (1.f / 256.f);
    float xn = dv / sqrtf(var + 1e-5f) * lng[t] + lnb[t];
    float ge = 0.5f * xn * (1.f + erff(xn / sqrtf(2.0f)));
    g_t[(size_t)row * 256 + t] = ge;
}

// fused L1-normalize + transpose: reads hh once, writes g_h[n][b][d][s]
// block = (b, 32-row strip of s); smem tile [32][517]
__global__ void hnorm_kernel() {
    extern __shared__ float hhs[];           // [32][517]
    __shared__ float den[2][32];
    int t = threadIdx.x;
    int b = blockIdx.y;
    int s0 = blockIdx.x * 32;
    // load 32 rows x 512 cols (float4)
    #pragma unroll
    for (int j = 0; j < 16; j++) {
        int idx4 = j * 256 + t;              // 0..4095
        int s = idx4 >> 7, c4 = idx4 & 127;
        float4 v = *(const float4*)(g_hh + ((size_t)(b * SS + s0 + s)) * 512 + c4 * 4);
        float* dst = &hhs[s * 517 + c4 * 4];
        dst[0] = v.x; dst[1] = v.y; dst[2] = v.z; dst[3] = v.w;
    }
    __syncthreads();
    // row L1 sums: warp w handles rows w, w+8, w+16, w+24
    {
        int w = t >> 5, lane = t & 31;
        #pragma unroll
        for (int rr = 0; rr < 4; rr++) {
            int s = w + rr * 8;
            #pragma unroll
            for (int n = 0; n < 2; n++) {
                float a = 0.f;
                #pragma unroll
                for (int k = 0; k < 8; k++)
                    a += fabsf(hhs[s * 517 + n * 256 + lane + k * 32]);
                for (int o = 16; o > 0; o >>= 1) a += __shfl_down_sync(0xffffffffu, a, o);
                if (lane == 0) den[n][s] = a + 1e-8f;
            }
        }
    }
    __syncthreads();
    // write transposed: g_h[n][b][d][s0+sl] = hhs[sl][n*256+d] / den
    #pragma unroll
    for (int wv = 0; wv < 64; wv++) {
        int linear = wv * 256 + t;           // 0..16383
        int sl = linear & 31;
        int col = linear >> 5;               // 0..511
        int n = col >> 8, d = col & 255;
        float v = hhs[sl * 517 + col] / den[n][sl];
        g_h[((size_t)(n * BB + b) * 256 + d) * SS + s0 + sl] = v;
    }
}

// ---------------- fused FFT causal conv, channel-pair packing, radix-2^2 ----------------
// Padded smem indexing (FIDX) -> conflict-free butterflies and twiddle reads.
__global__ __launch_bounds__(1024, 1) void fftconv_fused() {
    extern __shared__ float2 smbuf[];
    float2* sa = smbuf;                 // FIDX space, SA_PAD
    float2* sb = smbuf + SA_PAD;        // FIDX space, SA_PAD
    float2* tw = smbuf + 2 * SA_PAD;    // FIDX space, TW_PAD
    int t = threadIdx.x;
    int pi = blockIdx.x;           // 0..1023
    int b = pi >> 7;
    int d0 = (pi & 127) * 2;
    const float* xp0 = g_z + (size_t)((b * 3 + 2) * 256 + d0) * SS;
    float* op = g_v + (size_t)(b * 256 + d0) * SS;

    for (int i = t; i < NF / 4; i += 1024) tw[FIDX(i)] = g_tw[i];
    for (int s = t; s < SS; s += 1024) sa[FIDX(s)] = make_float2(xp0[s], xp0[SS + s]);
    for (int s = SS + t; s < NF; s += 1024) sa[FIDX(s)] = make_float2(0.f, 0.f);

    #pragma unroll 1
    for (int iter = 0; iter < 2; iter++) {
        const float* fp = g_h + (size_t)iter * (BB * DD * SS) + (size_t)(b * 256 + d0) * SS;
        const float* zp = g_z + (size_t)((b * 3 + iter) * 256 + d0) * SS;
        for (int s = t; s < SS; s += 1024) sb[FIDX(s)] = make_float2(fp[s], fp[SS + s]);
        for (int s = SS + t; s < NF; s += 1024) sb[FIDX(s)] = make_float2(0.f, 0.f);
        __syncthreads();

        // forward: 6 radix-2^2 passes (halves H & H/2), H = 4096..4
        #pragma unroll 1
        for (int lg = 11; lg >= 1; lg -= 2) {
            int hh = 1 << lg;          // H/2
            int H = hh << 1;
            int ts1 = 1 << (11 - lg);  // NF/(2H)
            for (int u = t; u < NF / 4; u += 1024) {
                int j0 = u & (hh - 1);
                int p0 = ((u >> lg) << (lg + 2)) + j0;
                int i0 = FIDX(p0), i1 = FIDX(p0 + hh), i2 = FIDX(p0 + H), i3 = FIDX(p0 + H + hh);
                float2 w1 = tw[FIDX(j0 * ts1)];
                float2 w1b = make_float2(w1.y, -w1.x);
                float2 w2 = cmul(w1, w1);
                {
                    float2 a0 = sa[i0], a1 = sa[i1], a2 = sa[i2], a3 = sa[i3];
                    float2 t0 = cadd(a0, a2), u2 = cmul(csub(a0, a2), w1);
                    float2 t1 = cadd(a1, a3), u3 = cmul(csub(a1, a3), w1b);
                    sa[i0] = cadd(t0, t1);
                    sa[i1] = cmul(csub(t0, t1), w2);
                    sa[i2] = cadd(u2, u3);
                    sa[i3] = cmul(csub(u2, u3), w2);
                }
                {
                    float2 a0 = sb[i0], a1 = sb[i1], a2 = sb[i2], a3 = sb[i3];
                    float2 t0 = cadd(a0, a2), u2 = cmul(csub(a0, a2), w1);
                    float2 t1 = cadd(a1, a3), u3 = cmul(csub(a1, a3), w1b);
                    sb[i0] = cadd(t0, t1);
                    sb[i1] = cmul(csub(t0, t1), w2);
                    sb[i2] = cadd(u2, u3);
                    sb[i3] = cmul(csub(u2, u3), w2);
                }
            }
            __syncthreads();
        }
        // final forward radix-2 stage (half=1, w=1)
        for (int i = t; i < NF / 2; i += 1024) {
            int p0 = FIDX(2 * i), p1 = FIDX(2 * i + 1);
            float2 a = sa[p0], bq = sa[p1];
            sa[p0] = cadd(a, bq); sa[p1] = csub(a, bq);
            float2 c = sb[p0], dq = sb[p1];
            sb[p0] = cadd(c, dq); sb[p1] = csub(c, dq);
        }
        __syncthreads();

        // per-channel spectral product in bit-reversed domain, result packed into sa
        for (int k = t; k < NF / 2; k += 1024) {
            if (k == 0) {
                float2 A0 = sa[0], B0 = sb[0];
                sa[0] = make_float2(A0.x * B0.x, A0.y * B0.y);    // bin 0
                float2 A1 = sa[1], B1 = sb[1];
                sa[1] = make_float2(A1.x * B1.x, A1.y * B1.y);    // bin NF/2
            } else {
                int p = FIDX(__brev((unsigned)k) >> (32 - LOG2NF));
                int q = FIDX(__brev((unsigned)(NF - k)) >> (32 - LOG2NF));
                float2 A = sa[p], Ac = sa[q];
                float2 Bv = sb[p], Bc = sb[q];
                float Xr  = 0.5f * (A.x + Ac.x),  Xi  = 0.5f * (A.y - Ac.y);
                float Xpr = 0.5f * (A.y + Ac.y),  Xpi = 0.5f * (Ac.x - A.x);
                float Fr  = 0.5f * (Bv.x + Bc.x), Fi  = 0.5f * (Bv.y - Bc.y);
                float Fpr = 0.5f * (Bv.y + Bc.y), Fpi = 0.5f * (Bc.x - Bv.x);
                float Yr  = Xr * Fr - Xi * Fi,     Yi  = Xr * Fi + Xi * Fr;
                float Ypr = Xpr * Fpr - Xpi * Fpi, Ypi = Xpr * Fpi + Xpi * Fpr;
                sa[p] = make_float2(Yr - Ypi, Yi + Ypr);
                sa[q] = make_float2(Yr + Ypi, Ypr - Yi);
            }
        }
        __syncthreads();

        // inverse: first radix-2 stage (m=2, w=1)
        for (int i = t; i < NF / 2; i += 1024) {
            int p0 = FIDX(2 * i), p1 = FIDX(2 * i + 1);
            float2 a = sa[p0], bq = sa[p1];
            sa[p0] = cadd(a, bq); sa[p1] = csub(a, bq);
        }
        __syncthreads();
        // 6 radix-2^2 DIT passes, m = 4..4096 (stages m and 2m), conj twiddles
        #pragma unroll 1
        for (int lgm = 2; lgm <= 12; lgm += 2) {
            int m = 1 << lgm;
            int hm = m >> 1;
            int ts = NF >> (lgm + 1);   // NF/(2m)
            for (int u = t; u < NF / 4; u += 1024) {
                int j0 = u & (hm - 1);
                int p0 = ((u >> (lgm - 1)) << (lgm + 1)) + j0;
                int i0 = FIDX(p0), i1 = FIDX(p0 + hm), i2 = FIDX(p0 + m), i3 = FIDX(p0 + m + hm);
                float2 wb = tw[FIDX(j0 * ts)];
                float2 wm = cmul(wb, wb);
                float2 a0 = sa[i0], a1 = sa[i1], a2 = sa[i2], a3 = sa[i3];
                float2 t1 = cmulc(a1, wm);
                float2 o0 = cadd(a0, t1), o1 = csub(a0, t1);
                float2 t3 = cmulc(a3, wm);
                float2 o2 = cadd(a2, t3), o3 = csub(a2, t3);
                float2 c2 = cmulc(o2, wb);
                float2 cz = cmulc(o3, wb);
                float2 t2 = make_float2(-cz.y, cz.x);   // i * cz
                sa[i0] = cadd(o0, c2);
                sa[i2] = csub(o0, c2);
                sa[i1] = cadd(o1, t2);
                sa[i3] = csub(o1, t2);
            }
            __syncthreads();
        }

        const float scale = 1.0f / (8192.0f * 8192.0f);
        if (iter == 0) {
            // v = z0 * conv; becomes x for iter 1, kept in smem
            for (int s = t; s < SS; s += 1024) {
                float2 r = sa[FIDX(s)];
                sa[FIDX(s)] = make_float2(zp[s] * (r.x * scale), zp[SS + s] * (r.y * scale));
            }
            for (int s = SS + t; s < NF; s += 1024) sa[FIDX(s)] = make_float2(0.f, 0.f);
        } else {
            for (int s = t; s < SS; s += 1024) {
                float2 r = sa[FIDX(s)];
                op[s]      = zp[s]      * (r.x * scale);
                op[SS + s] = zp[SS + s] * (r.y * scale);
            }
        }
    }
}

// transpose v[b][d][s] -> vT[b*SS+s][d]
__global__ void vtrans_kernel() {
    __shared__ float tile[32][33];
    int tx = threadIdx.x & 31, ty = threadIdx.x >> 5;   // 32 x 8
    int s0 = blockIdx.x * 32;
    int d0 = blockIdx.y * 32;
    int b = blockIdx.z;
    #pragma unroll
    for (int r = 0; r < 4; r++) {
        int d = d0 + ty + r * 8;
        tile[ty + r * 8][tx] = g_v[(size_t)(b * 256 + d) * SS + s0 + tx];
    }
    __syncthreads();
    #pragma unroll
    for (int r = 0; r < 4; r++) {
        int s = s0 + ty + r * 8;
        g_vT[(size_t)(b * SS + s) * 256 + d0 + tx] = tile[tx][ty + r * 8];
    }
}

// ---------------- launch ----------------
extern "C" void kernel_launch(void* const* d_in, const int* in_sizes, int n_in,
                              void* d_out, int out_size) {
    const float* emb   = (const float*)d_in[0];
    const int*   pos   = (const int*)d_in[1];
    const float* Wproj = (const float*)d_in[2];
    const float* convw = (const float*)d_in[3];
    const float* convb = (const float*)d_in[4];
    const float* W1    = (const float*)d_in[5];
    const float* b1    = (const float*)d_in[6];
    const float* lng   = (const float*)d_in[7];
    const float* lnb   = (const float*)d_in[8];
    const float* W2    = (const float*)d_in[9];
    const float* b2    = (const float*)d_in[10];
    const float* ffs   = (const float*)d_in[11];
    const float* Wout  = (const float*)d_in[12];
    const float* bout  = (const float*)d_in[13];
    float* out = (float*)d_out;

    const int fft_smem = (2 * SA_PAD + TW_PAD) * 8;          // 156672 bytes
    cudaFuncSetAttribute(fftconv_fused, cudaFuncAttributeMaxDynamicSharedMemorySize, fft_smem);
    const int hn_smem = 32 * 517 * 4;                        // 66176 bytes
    cudaFuncSetAttribute(hnorm_kernel, cudaFuncAttributeMaxDynamicSharedMemorySize, hn_smem);

    tw_init_kernel<<<8, 256>>>();
    minpos_kernel<<<BB, 256>>>(pos);
    wc_gemm<<<dim3(12, 4, 3), 256>>>(Wproj, convw);
    rope_kernel<<<BB * SS, 128>>>(emb, pos);
    zconv_mma<<<dim3(12, 256), 256>>>(emb, convb, pos);
    ffn_mma<256, false, false><<<dim3(4, 256), 256>>>(0, W1, b1, nullptr, nullptr, nullptr);
    ln_gelu_kernel<<<BB * SS, 256>>>(lng, lnb);
    ffn_mma<512, true, false><<<dim3(8, 256), 256>>>(1, W2, b2, ffs, nullptr, nullptr);
    hnorm_kernel<<<dim3(SS / 32, BB), 256, hn_smem>>>();
    fftconv_fused<<<BB * DD / 2, 1024, fft_smem>>>();
    vtrans_kernel<<<dim3(128, 8, 8), 256>>>();
    ffn_mma<256, false, true><<<dim3(4, 256), 256>>>(2, Wout, bout, nullptr, pos, out);
}

// round 10
// speedup vs baseline: 4.3015x; 1.1085x over previous
#include <cuda_runtime.h>
#include <cuda_bf16.h>
#include <math.h>
#include <stdint.h>

// Problem constants
#define BB 8
#define SS 4096
#define DD 256
#define GG 3
#define NORD 2
#define NF 8192          // FFT length = 2*S
#define LOG2NF 13

// padded smem index for FFT
#define FIDX(i) ((i) + ((i) >> 4))
#define SA_PAD 8704
#define TW_PAD 2176

// ---------------- device scratch (static, no allocation) ----------------
__device__ float  g_minpos[BB];
__device__ float  g_theta[128];
__device__ float2 g_tw[NF/4];
// bf16 split activations (hi / lo), k-adjacent layout [row][256]
__device__ __nv_bfloat16 g_embh[BB * SS * 256];
__device__ __nv_bfloat16 g_embl[BB * SS * 256];
__device__ __nv_bfloat16 g_th[BB * SS * 256];
__device__ __nv_bfloat16 g_tl[BB * SS * 256];
__device__ __nv_bfloat16 g_vTh[BB * SS * 256];
__device__ __nv_bfloat16 g_vTl[BB * SS * 256];
// K-pair-packed bf16 weights: u32 = bf16(k even) | bf16(k odd)<<16, layout [K/2][N]
__device__ uint32_t g_Wch[384 * 768];
__device__ uint32_t g_Wcl[384 * 768];
__device__ uint32_t g_W1h[128 * 256];
__device__ uint32_t g_W1l[128 * 256];
__device__ uint32_t g_W2h[128 * 512];
__device__ uint32_t g_W2l[128 * 512];
__device__ uint32_t g_Woh[128 * 256];
__device__ uint32_t g_Wol[128 * 256];
// f32 intermediates
__device__ float  g_z[BB * GG * DD * SS];          // [b][g][d][s]
__device__ float  g_h1[BB * SS * DD];
__device__ float  g_hh[BB * SS * 2 * DD];
__device__ float  g_h[NORD * BB * DD * SS];        // [n][b][d][s]
__device__ float  g_v[BB * DD * SS];               // [b][d][s]

// ---------------- helpers ----------------
__device__ __forceinline__ uint32_t sptr(const void* p) {
    return (uint32_t)__cvta_generic_to_shared(p);
}
__device__ __forceinline__ void cpa16(uint32_t dst, const void* src, int sz) {
    asm volatile("cp.async.ca.shared.global [%0], [%1], 16, %2;\n"
                 :: "r"(dst), "l"(src), "r"(sz));
}
__device__ __forceinline__ void cpa_commit() {
    asm volatile("cp.async.commit_group;\n" ::: "memory");
}
__device__ __forceinline__ void cpa_wait1() {
    asm volatile("cp.async.wait_group 1;\n" ::: "memory");
}
__device__ __forceinline__ void cpa_wait0() {
    asm volatile("cp.async.wait_group 0;\n" ::: "memory");
}
__device__ __forceinline__ uint32_t pk2(__nv_bfloat16 a, __nv_bfloat16 b) {
    return (uint32_t)__bfloat16_as_ushort(a) | ((uint32_t)__bfloat16_as_ushort(b) << 16);
}
__device__ __forceinline__ void mma16(float c[4], const uint32_t a[4], const uint32_t b[2]) {
    asm volatile(
        "mma.sync.aligned.m16n8k16.row.col.f32.bf16.bf16.f32 "
        "{%0,%1,%2,%3}, {%4,%5,%6,%7}, {%8,%9}, {%0,%1,%2,%3};\n"
        : "+f"(c[0]), "+f"(c[1]), "+f"(c[2]), "+f"(c[3])
        : "r"(a[0]), "r"(a[1]), "r"(a[2]), "r"(a[3]), "r"(b[0]), "r"(b[1]));
}
__device__ __forceinline__ float2 cmul(float2 a, float2 b) {
    return make_float2(a.x * b.x - a.y * b.y, a.x * b.y + a.y * b.x);
}
__device__ __forceinline__ float2 cmulc(float2 a, float2 w) {
    return make_float2(a.x * w.x + a.y * w.y, a.y * w.x - a.x * w.y);
}
__device__ __forceinline__ float2 cadd(float2 a, float2 b) { return make_float2(a.x + b.x, a.y + b.y); }
__device__ __forceinline__ float2 csub(float2 a, float2 b) { return make_float2(a.x - b.x, a.y - b.y); }

// One BK=16 slab, warp tile 32x32, bf16x3 (hi*hi + hi*lo + lo*hi)
__device__ __forceinline__ void compute_slab_bf(
    const __nv_bfloat16 (*A_h)[24], const __nv_bfloat16 (*A_l)[24],
    const uint32_t (*B_h)[72], const uint32_t (*B_l)[72],
    int wm, int wn, int g, int tig, float acc[2][4][4])
{
    uint32_t ah[2][4], al[2][4];
    #pragma unroll
    for (int mt = 0; mt < 2; mt++) {
        int rm = wm * 32 + mt * 16;
        ah[mt][0] = *(const uint32_t*)&A_h[rm + g][2 * tig];
        ah[mt][1] = *(const uint32_t*)&A_h[rm + g + 8][2 * tig];
        ah[mt][2] = *(const uint32_t*)&A_h[rm + g][2 * tig + 8];
        ah[mt][3] = *(const uint32_t*)&A_h[rm + g + 8][2 * tig + 8];
        al[mt][0] = *(const uint32_t*)&A_l[rm + g][2 * tig];
        al[mt][1] = *(const uint32_t*)&A_l[rm + g + 8][2 * tig];
        al[mt][2] = *(const uint32_t*)&A_l[rm + g][2 * tig + 8];
        al[mt][3] = *(const uint32_t*)&A_l[rm + g + 8][2 * tig + 8];
    }
    uint32_t bh[4][2], bl[4][2];
    #pragma unroll
    for (int nt = 0; nt < 4; nt++) {
        int cn = wn * 32 + nt * 8 + g;
        bh[nt][0] = B_h[tig][cn];     bh[nt][1] = B_h[tig + 4][cn];
        bl[nt][0] = B_l[tig][cn];     bl[nt][1] = B_l[tig + 4][cn];
    }
    #pragma unroll
    for (int mt = 0; mt < 2; mt++)
        #pragma unroll
        for (int nt = 0; nt < 4; nt++) {
            mma16(acc[mt][nt], ah[mt], bh[nt]);
            mma16(acc[mt][nt], ah[mt], bl[nt]);
            mma16(acc[mt][nt], al[mt], bh[nt]);
        }
}

// ---------------- split precompute kernels ----------------
__global__ void emb_split_kernel(const float* __restrict__ emb) {
    int i = blockIdx.x * 256 + threadIdx.x;
    float v = emb[i];
    __nv_bfloat16 h = __float2bfloat16(v);
    g_embh[i] = h;
    g_embl[i] = __float2bfloat16(v - __bfloat162float(h));
}

__global__ void wsplit_kernel(const float* __restrict__ W1, const float* __restrict__ W2,
                              const float* __restrict__ Wout) {
    int idx = blockIdx.x * 256 + threadIdx.x;
    const float* src; uint32_t *dh, *dl; int LDN, loc;
    if (idx < 32768)       { src = W1;   dh = g_W1h; dl = g_W1l; LDN = 256; loc = idx; }
    else if (idx < 98304)  { src = W2;   dh = g_W2h; dl = g_W2l; LDN = 512; loc = idx - 32768; }
    else                   { src = Wout; dh = g_Woh; dl = g_Wol; LDN = 256; loc = idx - 98304; }
    int kp = loc / LDN, n = loc % LDN;
    float v0 = src[(size_t)(2 * kp) * LDN + n];
    float v1 = src[(size_t)(2 * kp + 1) * LDN + n];
    __nv_bfloat16 h0 = __float2bfloat16(v0), h1 = __float2bfloat16(v1);
    dh[loc] = pk2(h0, h1);
    dl[loc] = pk2(__float2bfloat16(v0 - __bfloat162float(h0)),
                  __float2bfloat16(v1 - __bfloat162float(h1)));
}

// ---------------- init kernels ----------------
__global__ void tw_init_kernel() {
    int k = blockIdx.x * blockDim.x + threadIdx.x;
    if (k < NF/4) {
        double a = -2.0 * 3.14159265358979323846 * (double)k / (double)NF;
        double s, c;
        sincos(a, &s, &c);
        g_tw[k] = make_float2((float)c, (float)s);
    }
    if (k < 128) {
        float frac = (float)k * (1.0f / 128.0f);
        g_theta[k] = 1.0f / powf(10000.0f, frac);
    }
}

__global__ void minpos_kernel(const int* __restrict__ pos) {
    int b = blockIdx.x;
    int t = threadIdx.x;
    int local = 0x7fffffff;
    for (int s = t; s < SS; s += blockDim.x) {
        int p = pos[b * SS + s];
        if (p != -1) local = min(local, p);
    }
    for (int o = 16; o > 0; o >>= 1) local = min(local, __shfl_down_sync(0xffffffffu, local, o));
    __shared__ int wmin[8];
    if ((t & 31) == 0) wmin[t >> 5] = local;
    __syncthreads();
    if (t == 0) {
        int m = wmin[0];
        for (int i = 1; i < (int)(blockDim.x >> 5); i++) m = min(m, wmin[i]);
        g_minpos[b] = (float)m;
    }
}

// ---------------- SIMT gemm for Wc precompute, packed-split epilogue ----------------
#define GEMM_CORE()                                                        \
    __syncthreads();                                                       \
    _Pragma("unroll")                                                      \
    for (int kk = 0; kk < 16; kk++) {                                      \
        float4 af = *(const float4*)&As[kk][ty * 4];                       \
        float4 bf = *(const float4*)&Bs[kk][tx * 4];                       \
        float ar[4] = {af.x, af.y, af.z, af.w};                            \
        float br[4] = {bf.x, bf.y, bf.z, bf.w};                            \
        _Pragma("unroll")                                                  \
        for (int i = 0; i < 4; i++)                                        \
            _Pragma("unroll")                                              \
            for (int j = 0; j < 4; j++) acc[i][j] += ar[i] * br[j];        \
    }                                                                      \
    __syncthreads();

// Wc[tap*256+d][c] = sum_i Wproj[d][g*256+i] * conv_w[c][i][tap]; write packed bf16 pairs
__global__ void wc_gemm(const float* __restrict__ Wproj, const float* __restrict__ convw) {
    __shared__ __align__(16) float As[16][64];
    __shared__ __align__(16) float Bs[16][64];
    int t = threadIdx.x;
    int tx = t & 15, ty = t >> 4;
    int n0 = blockIdx.x * 64;         // c
    int m0 = blockIdx.y * 64;         // d
    int tap = blockIdx.z;
    int g = n0 >> 8;
    int am = t >> 2, akq = t & 3;
    int bk = t >> 4, bnq = t & 15;
    float acc[4][4] = {};
    for (int k0 = 0; k0 < 256; k0 += 16) {
        float4 av = *(const float4*)(Wproj + (size_t)(m0 + am) * 768 + g * 256 + k0 + akq * 4);
        As[akq * 4 + 0][am] = av.x;
        As[akq * 4 + 1][am] = av.y;
        As[akq * 4 + 2][am] = av.z;
        As[akq * 4 + 3][am] = av.w;
        int i = k0 + bk;
        int c = n0 + bnq * 4;
        #pragma unroll
        for (int e = 0; e < 4; e++)
            Bs[bk][bnq * 4 + e] = convw[(size_t)(c + e) * 768 + i * 3 + tap];
        GEMM_CORE()
    }
    #pragma unroll
    for (int i = 0; i < 4; i += 2) {
        int kglob = tap * 256 + m0 + ty * 4 + i;
        size_t kpg = (size_t)(kglob >> 1);
        #pragma unroll
        for (int j = 0; j < 4; j++) {
            float v0 = acc[i][j], v1 = acc[i + 1][j];
            __nv_bfloat16 h0 = __float2bfloat16(v0), h1 = __float2bfloat16(v1);
            int cidx = n0 + tx * 4 + j;
            g_Wch[kpg * 768 + cidx] = pk2(h0, h1);
            g_Wcl[kpg * 768 + cidx] = pk2(__float2bfloat16(v0 - __bfloat162float(h0)),
                                          __float2bfloat16(v1 - __bfloat162float(h1)));
        }
    }
}

// ---------------- rope (writes bf16 split) ----------------
__global__ void rope_kernel(const float* __restrict__ emb, const int* __restrict__ pos) {
    int row = blockIdx.x;
    int i = threadIdx.x;             // pair index 0..127
    int b = row >> 12;
    float2 xv = *(const float2*)(emb + (size_t)row * 256 + 2 * i);
    float theta = g_theta[i];
    int p = pos[row];
    float adj = (p == -1) ? -1.0f : ((float)p - g_minpos[b]);
    float ang = adj * theta;
    float sn, cs;
    sincosf(ang, &sn, &cs);
    float rx = xv.x * cs - xv.y * sn;
    float ry = xv.x * sn + xv.y * cs;
    __nv_bfloat16 hx = __float2bfloat16(rx), hy = __float2bfloat16(ry);
    size_t o = (size_t)row * 256 + 2 * i;
    *(uint32_t*)(g_th + o) = pk2(hx, hy);
    *(uint32_t*)(g_tl + o) = pk2(__float2bfloat16(rx - __bfloat162float(hx)),
                                 __float2bfloat16(ry - __bfloat162float(hy)));
}

// ---------------- bf16x3 MMA GEMM: zconv (im2col A from emb split) ----------------
__global__ __launch_bounds__(256, 2) void zconv_mma(
    const float* __restrict__ convb, const int* __restrict__ pos)
{
    __shared__ __align__(16) char smraw[33792];
    __nv_bfloat16 (*Ah)[128][24] = reinterpret_cast<__nv_bfloat16(*)[128][24]>(smraw);
    __nv_bfloat16 (*Al)[128][24] = reinterpret_cast<__nv_bfloat16(*)[128][24]>(smraw + 12288);
    uint32_t (*Bh)[8][72] = reinterpret_cast<uint32_t(*)[8][72]>(smraw + 24576);
    uint32_t (*Bl)[8][72] = reinterpret_cast<uint32_t(*)[8][72]>(smraw + 29184);
    int t = threadIdx.x;
    int w = t >> 5, lane = t & 31, g = lane >> 2, tig = lane & 3;
    int wm = w & 3, wn = w >> 2;
    int n0 = blockIdx.x * 64;
    int by = blockIdx.y;
    int b = by >> 5;
    int s0 = (by & 31) * 128;
    float acc[2][4][4] = {};

    auto issue = [&](int slab, int stage) {
        int k0 = slab * 16;
        int tap = k0 >> 8;
        int dbase = k0 & 255;
        #pragma unroll
        for (int p = 0; p < 2; p++) {
            int idx = t + p * 256;
            int r = idx >> 2, q = idx & 3;
            int chunk = q & 1, arr = q >> 1;
            int sp = s0 + r + tap - 1;
            int ok = (sp >= 0 && sp < SS);
            int spc = min(max(sp, 0), SS - 1);
            const __nv_bfloat16* src = (arr ? g_embl : g_embh)
                + (size_t)(b * SS + spc) * 256 + dbase + chunk * 8;
            cpa16(sptr(arr ? &Al[stage][r][chunk * 8] : &Ah[stage][r][chunk * 8]), src, ok ? 16 : 0);
        }
        {
            int row = t >> 5;
            int arr = (t >> 4) & 1, chunk = t & 15;
            size_t kpg = (size_t)((k0 >> 1) + row);
            const uint32_t* src = (arr ? g_Wcl : g_Wch) + kpg * 768 + n0 + chunk * 4;
            cpa16(sptr(arr ? &Bl[stage][row][chunk * 4] : &Bh[stage][row][chunk * 4]), src, 16);
        }
        cpa_commit();
    };

    issue(0, 0);
    const int KS = 48;
    for (int j = 0; j < KS; j++) {
        int st = j & 1;
        if (j + 1 < KS) { issue(j + 1, st ^ 1); cpa_wait1(); }
        else cpa_wait0();
        __syncthreads();
        compute_slab_bf(Ah[st], Al[st], Bh[st], Bl[st], wm, wn, g, tig, acc);
        __syncthreads();
    }

    // staged epilogue: two 64s x 64c halves through smem scratch
    float (*sc)[65] = reinterpret_cast<float(*)[65]>(smraw);
    #pragma unroll
    for (int hs = 0; hs < 2; hs++) {
        if ((wm >> 1) == hs) {
            #pragma unroll
            for (int mt = 0; mt < 2; mt++) {
                int sl = (wm & 1) * 32 + mt * 16 + g;
                #pragma unroll
                for (int nt = 0; nt < 4; nt++) {
                    int cl = wn * 32 + nt * 8 + 2 * tig;
                    sc[cl][sl]         = acc[mt][nt][0];
                    sc[cl + 1][sl]     = acc[mt][nt][1];
                    sc[cl][sl + 8]     = acc[mt][nt][2];
                    sc[cl + 1][sl + 8] = acc[mt][nt][3];
                }
            }
        }
        __syncthreads();
        {
            int cl = t >> 2;
            int sl0 = (t & 3) * 16;
            int c = n0 + cl;
            float bias = __ldg(convb + c);
            size_t ch = (size_t)((b * 3 + (c >> 8)) * 256 + (c & 255)) * SS;
            int sbase = s0 + hs * 64 + sl0;
            #pragma unroll
            for (int e4 = 0; e4 < 4; e4++) {
                int s = sbase + e4 * 4;
                float4 v;
                v.x = (sc[cl][sl0 + e4 * 4 + 0] + bias) * ((pos[b * SS + s + 0] != -1) ? 1.f : 0.f);
                v.y = (sc[cl][sl0 + e4 * 4 + 1] + bias) * ((pos[b * SS + s + 1] != -1) ? 1.f : 0.f);
                v.z = (sc[cl][sl0 + e4 * 4 + 2] + bias) * ((pos[b * SS + s + 2] != -1) ? 1.f : 0.f);
                v.w = (sc[cl][sl0 + e4 * 4 + 3] + bias) * ((pos[b * SS + s + 3] != -1) ? 1.f : 0.f);
                *(float4*)(g_z + ch + s) = v;
            }
        }
        __syncthreads();
    }
}

// ---------------- bf16x3 MMA GEMM: ffn1/ffn2/out ----------------
// SEL=0: A=g_t*,  B=W1, C=g_h1 (LDN=256)
// SEL=1: A=g_t*,  B=W2, C=g_hh (LDN=512, scale)
// SEL=2: A=g_vT*, B=Wo, C=Cout (LDN=256, mask)
template<int SEL, int LDN, bool SCALE, bool MASK>
__global__ __launch_bounds__(256, 2) void ffn_mma(
    const float* __restrict__ bias, const float* __restrict__ scale,
    const int* __restrict__ pos, float* __restrict__ Cout)
{
    const __nv_bfloat16* Ahg = (SEL == 2) ? g_vTh : g_th;
    const __nv_bfloat16* Alg = (SEL == 2) ? g_vTl : g_tl;
    const uint32_t* Bhg = (SEL == 0) ? g_W1h : (SEL == 1) ? g_W2h : g_Woh;
    const uint32_t* Blg = (SEL == 0) ? g_W1l : (SEL == 1) ? g_W2l : g_Wol;
    float* C = (SEL == 0) ? g_h1 : (SEL == 1) ? g_hh : Cout;

    __shared__ __align__(16) char smraw[33792];
    __nv_bfloat16 (*Ah)[128][24] = reinterpret_cast<__nv_bfloat16(*)[128][24]>(smraw);
    __nv_bfloat16 (*Al)[128][24] = reinterpret_cast<__nv_bfloat16(*)[128][24]>(smraw + 12288);
    uint32_t (*Bh)[8][72] = reinterpret_cast<uint32_t(*)[8][72]>(smraw + 24576);
    uint32_t (*Bl)[8][72] = reinterpret_cast<uint32_t(*)[8][72]>(smraw + 29184);
    int t = threadIdx.x;
    int w = t >> 5, lane = t & 31, g = lane >> 2, tig = lane & 3;
    int wm = w & 3, wn = w >> 2;
    int n0 = blockIdx.x * 64;
    int r0 = blockIdx.y * 128;
    float acc[2][4][4] = {};

    auto issue = [&](int slab, int stage) {
        int k0 = slab * 16;
        #pragma unroll
        for (int p = 0; p < 2; p++) {
            int idx = t + p * 256;
            int r = idx >> 2, q = idx & 3;
            int chunk = q & 1, arr = q >> 1;
            const __nv_bfloat16* src = (arr ? Alg : Ahg)
                + (size_t)(r0 + r) * 256 + k0 + chunk * 8;
            cpa16(sptr(arr ? &Al[stage][r][chunk * 8] : &Ah[stage][r][chunk * 8]), src, 16);
        }
        {
            int row = t >> 5;
            int arr = (t >> 4) & 1, chunk = t & 15;
            size_t kpg = (size_t)((k0 >> 1) + row);
            const uint32_t* src = (arr ? Blg : Bhg) + kpg * LDN + n0 + chunk * 4;
            cpa16(sptr(arr ? &Bl[stage][row][chunk * 4] : &Bh[stage][row][chunk * 4]), src, 16);
        }
        cpa_commit();
    };

    issue(0, 0);
    const int KS = 16;
    for (int j = 0; j < KS; j++) {
        int st = j & 1;
        if (j + 1 < KS) { issue(j + 1, st ^ 1); cpa_wait1(); }
        else cpa_wait0();
        __syncthreads();
        compute_slab_bf(Ah[st], Al[st], Bh[st], Bl[st], wm, wn, g, tig, acc);
        __syncthreads();
    }

    #pragma unroll
    for (int mt = 0; mt < 2; mt++) {
        int ra = r0 + wm * 32 + mt * 16 + g;
        int rb = ra + 8;
        float ma = 1.f, mb = 1.f;
        if (MASK) {
            ma = (pos[ra] != -1) ? 1.f : 0.f;
            mb = (pos[rb] != -1) ? 1.f : 0.f;
        }
        #pragma unroll
        for (int nt = 0; nt < 4; nt++) {
            int cn = n0 + wn * 32 + nt * 8 + 2 * tig;
            float2 bi = *(const float2*)(bias + cn);
            float sx = 1.f, sy = 1.f;
            if (SCALE) {
                float2 sc2 = *(const float2*)(scale + cn);
                sx = sc2.x; sy = sc2.y;
            }
            float2 va, vb;
            va.x = (acc[mt][nt][0] + bi.x) * sx * ma;
            va.y = (acc[mt][nt][1] + bi.y) * sy * ma;
            vb.x = (acc[mt][nt][2] + bi.x) * sx * mb;
            vb.y = (acc[mt][nt][3] + bi.y) * sy * mb;
            *(float2*)(C + (size_t)ra * LDN + cn) = va;
            *(float2*)(C + (size_t)rb * LDN + cn) = vb;
        }
    }
}

// LayerNorm (two-pass) + exact gelu: reads g_h1, writes bf16 split to g_th/g_tl
__global__ void ln_gelu_kernel(const float* __restrict__ lng, const float* __restrict__ lnb) {
    int row = blockIdx.x;
    int t = threadIdx.x;
    float v = g_h1[(size_t)row * 256 + t];
    __shared__ float ws[8];
    float s1 = v;
    for (int o = 16; o > 0; o >>= 1) s1 += __shfl_down_sync(0xffffffffu, s1, o);
    if ((t & 31) == 0) ws[t >> 5] = s1;
    __syncthreads();
    if (t == 0) {
        float a = 0.f;
        for (int i = 0; i < 8; i++) a += ws[i];
        ws[0] = a;
    }
    __syncthreads();
    float mu = ws[0] * (1.f / 256.f);
    __syncthreads();
    float dv = v - mu;
    float s2 = dv * dv;
    for (int o = 16; o > 0; o >>= 1) s2 += __shfl_down_sync(0xffffffffu, s2, o);
    if ((t & 31) == 0) ws[t >> 5] = s2;
    __syncthreads();
    if (t == 0) {
        float a = 0.f;
        for (int i = 0; i < 8; i++) a += ws[i];
        ws[0] = a;
    }
    __syncthreads();
    float var = ws[0] * (1.f / 256.f);
    float xn = dv / sqrtf(var + 1e-5f) * lng[t] + lnb[t];
    float ge = 0.5f * xn * (1.f + erff(xn / sqrtf(2.0f)));
    __nv_bfloat16 h = __float2bfloat16(ge);
    g_th[(size_t)row * 256 + t] = h;
    g_tl[(size_t)row * 256 + t] = __float2bfloat16(ge - __bfloat162float(h));
}

// fused L1-normalize + transpose: reads hh once, writes g_h[n][b][d][s]
__global__ void hnorm_kernel() {
    extern __shared__ float hhs[];           // [32][517]
    __shared__ float den[2][32];
    int t = threadIdx.x;
    int b = blockIdx.y;
    int s0 = blockIdx.x * 32;
    #pragma unroll
    for (int j = 0; j < 16; j++) {
        int idx4 = j * 256 + t;
        int s = idx4 >> 7, c4 = idx4 & 127;
        float4 v = *(const float4*)(g_hh + ((size_t)(b * SS + s0 + s)) * 512 + c4 * 4);
        float* dst = &hhs[s * 517 + c4 * 4];
        dst[0] = v.x; dst[1] = v.y; dst[2] = v.z; dst[3] = v.w;
    }
    __syncthreads();
    {
        int w = t >> 5, lane = t & 31;
        #pragma unroll
        for (int rr = 0; rr < 4; rr++) {
            int s = w + rr * 8;
            #pragma unroll
            for (int n = 0; n < 2; n++) {
                float a = 0.f;
                #pragma unroll
                for (int k = 0; k < 8; k++)
                    a += fabsf(hhs[s * 517 + n * 256 + lane + k * 32]);
                for (int o = 16; o > 0; o >>= 1) a += __shfl_down_sync(0xffffffffu, a, o);
                if (lane == 0) den[n][s] = a + 1e-8f;
            }
        }
    }
    __syncthreads();
    #pragma unroll
    for (int wv = 0; wv < 64; wv++) {
        int linear = wv * 256 + t;
        int sl = linear & 31;
        int col = linear >> 5;
        int n = col >> 8, d = col & 255;
        float v = hhs[sl * 517 + col] / den[n][sl];
        g_h[((size_t)(n * BB + b) * 256 + d) * SS + s0 + sl] = v;
    }
}

// ---------------- fused FFT causal conv (unchanged from R9) ----------------
__global__ __launch_bounds__(1024, 1) void fftconv_fused() {
    extern __shared__ float2 smbuf[];
    float2* sa = smbuf;
    float2* sb = smbuf + SA_PAD;
    float2* tw = smbuf + 2 * SA_PAD;
    int t = threadIdx.x;
    int pi = blockIdx.x;
    int b = pi >> 7;
    int d0 = (pi & 127) * 2;
    const float* xp0 = g_z + (size_t)((b * 3 + 2) * 256 + d0) * SS;
    float* op = g_v + (size_t)(b * 256 + d0) * SS;

    for (int i = t; i < NF / 4; i += 1024) tw[FIDX(i)] = g_tw[i];
    for (int s = t; s < SS; s += 1024) sa[FIDX(s)] = make_float2(xp0[s], xp0[SS + s]);
    for (int s = SS + t; s < NF; s += 1024) sa[FIDX(s)] = make_float2(0.f, 0.f);

    #pragma unroll 1
    for (int iter = 0; iter < 2; iter++) {
        const float* fp = g_h + (size_t)iter * (BB * DD * SS) + (size_t)(b * 256 + d0) * SS;
        const float* zp = g_z + (size_t)((b * 3 + iter) * 256 + d0) * SS;
        for (int s = t; s < SS; s += 1024) sb[FIDX(s)] = make_float2(fp[s], fp[SS + s]);
        for (int s = SS + t; s < NF; s += 1024) sb[FIDX(s)] = make_float2(0.f, 0.f);
        __syncthreads();

        #pragma unroll 1
        for (int lg = 11; lg >= 1; lg -= 2) {
            int hh = 1 << lg;
            int H = hh << 1;
            int ts1 = 1 << (11 - lg);
            for (int u = t; u < NF / 4; u += 1024) {
                int j0 = u & (hh - 1);
                int p0 = ((u >> lg) << (lg + 2)) + j0;
                int i0 = FIDX(p0), i1 = FIDX(p0 + hh), i2 = FIDX(p0 + H), i3 = FIDX(p0 + H + hh);
                float2 w1 = tw[FIDX(j0 * ts1)];
                float2 w1b = make_float2(w1.y, -w1.x);
                float2 w2 = cmul(w1, w1);
                {
                    float2 a0 = sa[i0], a1 = sa[i1], a2 = sa[i2], a3 = sa[i3];
                    float2 t0 = cadd(a0, a2), u2 = cmul(csub(a0, a2), w1);
                    float2 t1 = cadd(a1, a3), u3 = cmul(csub(a1, a3), w1b);
                    sa[i0] = cadd(t0, t1);
                    sa[i1] = cmul(csub(t0, t1), w2);
                    sa[i2] = cadd(u2, u3);
                    sa[i3] = cmul(csub(u2, u3), w2);
                }
                {
                    float2 a0 = sb[i0], a1 = sb[i1], a2 = sb[i2], a3 = sb[i3];
                    float2 t0 = cadd(a0, a2), u2 = cmul(csub(a0, a2), w1);
                    float2 t1 = cadd(a1, a3), u3 = cmul(csub(a1, a3), w1b);
                    sb[i0] = cadd(t0, t1);
                    sb[i1] = cmul(csub(t0, t1), w2);
                    sb[i2] = cadd(u2, u3);
                    sb[i3] = cmul(csub(u2, u3), w2);
                }
            }
            __syncthreads();
        }
        for (int i = t; i < NF / 2; i += 1024) {
            int p0 = FIDX(2 * i), p1 = FIDX(2 * i + 1);
            float2 a = sa[p0], bq = sa[p1];
            sa[p0] = cadd(a, bq); sa[p1] = csub(a, bq);
            float2 c = sb[p0], dq = sb[p1];
            sb[p0] = cadd(c, dq); sb[p1] = csub(c, dq);
        }
        __syncthreads();

        for (int k = t; k < NF / 2; k += 1024) {
            if (k == 0) {
                float2 A0 = sa[0], B0 = sb[0];
                sa[0] = make_float2(A0.x * B0.x, A0.y * B0.y);
                float2 A1 = sa[1], B1 = sb[1];
                sa[1] = make_float2(A1.x * B1.x, A1.y * B1.y);
            } else {
                int p = FIDX(__brev((unsigned)k) >> (32 - LOG2NF));
                int q = FIDX(__brev((unsigned)(NF - k)) >> (32 - LOG2NF));
                float2 A = sa[p], Ac = sa[q];
                float2 Bv = sb[p], Bc = sb[q];
                float Xr  = 0.5f * (A.x + Ac.x),  Xi  = 0.5f * (A.y - Ac.y);
                float Xpr = 0.5f * (A.y + Ac.y),  Xpi = 0.5f * (Ac.x - A.x);
                float Fr  = 0.5f * (Bv.x + Bc.x), Fi  = 0.5f * (Bv.y - Bc.y);
                float Fpr = 0.5f * (Bv.y + Bc.y), Fpi = 0.5f * (Bc.x - Bv.x);
                float Yr  = Xr * Fr - Xi * Fi,     Yi  = Xr * Fi + Xi * Fr;
                float Ypr = Xpr * Fpr - Xpi * Fpi, Ypi = Xpr * Fpi + Xpi * Fpr;
                sa[p] = make_float2(Yr - Ypi, Yi + Ypr);
                sa[q] = make_float2(Yr + Ypi, Ypr - Yi);
            }
        }
        __syncthreads();

        for (int i = t; i < NF / 2; i += 1024) {
            int p0 = FIDX(2 * i), p1 = FIDX(2 * i + 1);
            float2 a = sa[p0], bq = sa[p1];
            sa[p0] = cadd(a, bq); sa[p1] = csub(a, bq);
        }
        __syncthreads();
        #pragma unroll 1
        for (int lgm = 2; lgm <= 12; lgm += 2) {
            int m = 1 << lgm;
            int hm = m >> 1;
            int ts = NF >> (lgm + 1);
            for (int u = t; u < NF / 4; u += 1024) {
                int j0 = u & (hm - 1);
                int p0 = ((u >> (lgm - 1)) << (lgm + 1)) + j0;
                int i0 = FIDX(p0), i1 = FIDX(p0 + hm), i2 = FIDX(p0 + m), i3 = FIDX(p0 + m + hm);
                float2 wb = tw[FIDX(j0 * ts)];
                float2 wm = cmul(wb, wb);
                float2 a0 = sa[i0], a1 = sa[i1], a2 = sa[i2], a3 = sa[i3];
                float2 t1 = cmulc(a1, wm);
                float2 o0 = cadd(a0, t1), o1 = csub(a0, t1);
                float2 t3 = cmulc(a3, wm);
                float2 o2 = cadd(a2, t3), o3 = csub(a2, t3);
                float2 c2 = cmulc(o2, wb);
                float2 cz = cmulc(o3, wb);
                float2 t2 = make_float2(-cz.y, cz.x);
                sa[i0] = cadd(o0, c2);
                sa[i2] = csub(o0, c2);
                sa[i1] = cadd(o1, t2);
                sa[i3] = csub(o1, t2);
            }
            __syncthreads();
        }

        const float scale = 1.0f / (8192.0f * 8192.0f);
        if (iter == 0) {
            for (int s = t; s < SS; s += 1024) {
                float2 r = sa[FIDX(s)];
                sa[FIDX(s)] = make_float2(zp[s] * (r.x * scale), zp[SS + s] * (r.y * scale));
            }
            for (int s = SS + t; s < NF; s += 1024) sa[FIDX(s)] = make_float2(0.f, 0.f);
        } else {
            for (int s = t; s < SS; s += 1024) {
                float2 r = sa[FIDX(s)];
                op[s]      = zp[s]      * (r.x * scale);
                op[SS + s] = zp[SS + s] * (r.y * scale);
            }
        }
    }
}

// transpose v[b][d][s] -> vT split (bf16 hi/lo) [b*SS+s][d]
__global__ void vtrans_kernel() {
    __shared__ float tile[32][33];
    int tx = threadIdx.x & 31, ty = threadIdx.x >> 5;
    int s0 = blockIdx.x * 32;
    int d0 = blockIdx.y * 32;
    int b = blockIdx.z;
    #pragma unroll
    for (int r = 0; r < 4; r++) {
        int d = d0 + ty + r * 8;
        tile[ty + r * 8][tx] = g_v[(size_t)(b * 256 + d) * SS + s0 + tx];
    }
    __syncthreads();
    #pragma unroll
    for (int r = 0; r < 4; r++) {
        int s = s0 + ty + r * 8;
        float v = tile[tx][ty + r * 8];
        __nv_bfloat16 h = __float2bfloat16(v);
        size_t o = (size_t)(b * SS + s) * 256 + d0 + tx;
        g_vTh[o] = h;
        g_vTl[o] = __float2bfloat16(v - __bfloat162float(h));
    }
}

// ---------------- launch ----------------
extern "C" void kernel_launch(void* const* d_in, const int* in_sizes, int n_in,
                              void* d_out, int out_size) {
    const float* emb   = (const float*)d_in[0];
    const int*   pos   = (const int*)d_in[1];
    const float* Wproj = (const float*)d_in[2];
    const float* convw = (const float*)d_in[3];
    const float* convb = (const float*)d_in[4];
    const float* W1    = (const float*)d_in[5];
    const float* b1    = (const float*)d_in[6];
    const float* lng   = (const float*)d_in[7];
    const float* lnb   = (const float*)d_in[8];
    const float* W2    = (const float*)d_in[9];
    const float* b2    = (const float*)d_in[10];
    const float* ffs   = (const float*)d_in[11];
    const float* Wout  = (const float*)d_in[12];
    const float* bout  = (const float*)d_in[13];
    float* out = (float*)d_out;

    const int fft_smem = (2 * SA_PAD + TW_PAD) * 8;
    cudaFuncSetAttribute(fftconv_fused, cudaFuncAttributeMaxDynamicSharedMemorySize, fft_smem);
    const int hn_smem = 32 * 517 * 4;
    cudaFuncSetAttribute(hnorm_kernel, cudaFuncAttributeMaxDynamicSharedMemorySize, hn_smem);

    emb_split_kernel<<<BB * SS * 256 / 256, 256>>>(emb);
    wsplit_kernel<<<512, 256>>>(W1, W2, Wout);
    wc_gemm<<<dim3(12, 4, 3), 256>>>(Wproj, convw);
    zconv_mma<<<dim3(12, 256), 256>>>(convb, pos);
    tw_init_kernel<<<8, 256>>>();
    minpos_kernel<<<BB, 256>>>(pos);
    rope_kernel<<<BB * SS, 128>>>(emb, pos);
    ffn_mma<0, 256, false, false><<<dim3(4, 256), 256>>>(b1, nullptr, nullptr, nullptr);
    ln_gelu_kernel<<<BB * SS, 256>>>(lng, lnb);
    ffn_mma<1, 512, true, false><<<dim3(8, 256), 256>>>(b2, ffs, nullptr, nullptr);
    hnorm_kernel<<<dim3(SS / 32, BB), 256, hn_smem>>>();
    fftconv_fused<<<BB * DD / 2, 1024, fft_smem>>>();
    vtrans_kernel<<<dim3(128, 8, 8), 256>>>();
    ffn_mma<2, 256, false, true><<<dim3(4, 256), 256>>>(bout, nullptr, pos, out);
}